// round 1
// baseline (speedup 1.0000x reference)
#include <cuda_runtime.h>
#include <math.h>

#define BB 2
#define TT 2048
#define DD 1024
#define HH 16
#define DH 64
#define NTOK (BB*TT)

// Scratch buffers (allocation is forbidden; __device__ globals are the sanctioned path)
__device__ float g_q[NTOK*DD];
__device__ float g_k[NTOK*DD];
__device__ float g_v[NTOK*DD];
__device__ float g_ctx[NTOK*DD];

// ---------------------------------------------------------------------------
// GEMM: C[M,N] = A[M,K] @ W[N,K]^T + bias[N]   (nn.Linear semantics)
// BM=BN=128, BK=16, 256 threads, 8x8 register micro-tile.
// ---------------------------------------------------------------------------
__global__ __launch_bounds__(256) void gemm_bias_kernel(
    const float* __restrict__ A, const float* __restrict__ W,
    const float* __restrict__ bias, float* __restrict__ C,
    int M, int N, int K)
{
    __shared__ float As[16][128];   // [k][m]
    __shared__ float Ws[16][128];   // [k][n]

    const int tid = threadIdx.x;
    const int tx  = tid & 15;       // column group
    const int ty  = tid >> 4;       // row group
    const int rowBase = blockIdx.y * 128;
    const int colBase = blockIdx.x * 128;

    float acc[8][8];
    #pragma unroll
    for (int i = 0; i < 8; i++)
        #pragma unroll
        for (int j = 0; j < 8; j++) acc[i][j] = 0.f;

    for (int kb = 0; kb < K; kb += 16) {
        // Stage A and W tiles (transposed to k-major) — 2 float4 each per thread
        #pragma unroll
        for (int i = 0; i < 2; i++) {
            int f  = tid + i*256;      // 0..511 float4 slots
            int r  = f >> 2;           // 0..127
            int c4 = (f & 3) << 2;     // 0,4,8,12
            float4 av = *(const float4*)(A + (size_t)(rowBase + r)*K + kb + c4);
            As[c4+0][r] = av.x; As[c4+1][r] = av.y;
            As[c4+2][r] = av.z; As[c4+3][r] = av.w;
            float4 wv = *(const float4*)(W + (size_t)(colBase + r)*K + kb + c4);
            Ws[c4+0][r] = wv.x; Ws[c4+1][r] = wv.y;
            Ws[c4+2][r] = wv.z; Ws[c4+3][r] = wv.w;
        }
        __syncthreads();

        #pragma unroll
        for (int k = 0; k < 16; k++) {
            float a[8], bv[8];
            *(float4*)(a)    = *(const float4*)&As[k][ty*8];
            *(float4*)(a+4)  = *(const float4*)&As[k][ty*8+4];
            *(float4*)(bv)   = *(const float4*)&Ws[k][tx*8];
            *(float4*)(bv+4) = *(const float4*)&Ws[k][tx*8+4];
            #pragma unroll
            for (int i = 0; i < 8; i++)
                #pragma unroll
                for (int j = 0; j < 8; j++)
                    acc[i][j] = fmaf(a[i], bv[j], acc[i][j]);
        }
        __syncthreads();
    }

    #pragma unroll
    for (int i = 0; i < 8; i++) {
        int row = rowBase + ty*8 + i;
        #pragma unroll
        for (int j4 = 0; j4 < 8; j4 += 4) {
            int col = colBase + tx*8 + j4;
            float4 st;
            st.x = acc[i][j4+0] + bias[col+0];
            st.y = acc[i][j4+1] + bias[col+1];
            st.z = acc[i][j4+2] + bias[col+2];
            st.w = acc[i][j4+3] + bias[col+3];
            *(float4*)(C + (size_t)row*N + col) = st;
        }
    }
}

// ---------------------------------------------------------------------------
// Flash attention (causal, fp32, head_dim=64).
// One CTA = one (b, h, 64-query tile). 256 threads as a 16x16 grid,
// each thread owns a 4x4 micro-tile of S / O. Row softmax stats reduced
// within 16-lane shfl segments (threads of one row-group are contiguous).
// ---------------------------------------------------------------------------
#define SSTR 68   // padded row stride (floats); 68*4B = 272B keeps float4 alignment

__global__ __launch_bounds__(256) void flash_attn_kernel()
{
    extern __shared__ float sm[];
    float* Qs = sm;               // [d][r]  d-major
    float* Ks = sm + 64*SSTR;     // [d][c]  d-major
    float* Vs = sm + 2*64*SSTR;   // [c][dv] natural
    float* Ps = sm + 3*64*SSTR;   // [c][r]  c-major

    const int tid = threadIdx.x;
    const int tx  = tid & 15;
    const int ty  = tid >> 4;
    // reverse q-tile order: heaviest (most k-tiles) blocks scheduled first
    const int qt = gridDim.x - 1 - blockIdx.x;
    const int h  = blockIdx.y;
    const int b  = blockIdx.z;
    const int qbase = qt * 64;

    // Load Q tile, transposed to [d][r], pre-scaled by 1/sqrt(64)
    #pragma unroll
    for (int i = 0; i < 4; i++) {
        int f  = tid + i*256;
        int r  = f >> 4;
        int d4 = (f & 15) << 2;
        float4 v = *(const float4*)(g_q + (size_t)(b*TT + qbase + r)*DD + h*DH + d4);
        Qs[(d4+0)*SSTR + r] = v.x * 0.125f;
        Qs[(d4+1)*SSTR + r] = v.y * 0.125f;
        Qs[(d4+2)*SSTR + r] = v.z * 0.125f;
        Qs[(d4+3)*SSTR + r] = v.w * 0.125f;
    }

    float m[4], l[4], o[4][4];
    #pragma unroll
    for (int i = 0; i < 4; i++) {
        m[i] = -INFINITY; l[i] = 0.f;
        #pragma unroll
        for (int j = 0; j < 4; j++) o[i][j] = 0.f;
    }

    for (int kt = 0; kt <= qt; kt++) {
        const int kbase = kt * 64;
        __syncthreads();   // protect Ks/Vs/Ps from prior-iteration readers

        // Stage K (transposed [d][c]) and V (natural [c][dv])
        #pragma unroll
        for (int i = 0; i < 4; i++) {
            int f  = tid + i*256;
            int r  = f >> 4;
            int d4 = (f & 15) << 2;
            size_t gofs = (size_t)(b*TT + kbase + r)*DD + h*DH + d4;
            float4 kv = *(const float4*)(g_k + gofs);
            Ks[(d4+0)*SSTR + r] = kv.x;
            Ks[(d4+1)*SSTR + r] = kv.y;
            Ks[(d4+2)*SSTR + r] = kv.z;
            Ks[(d4+3)*SSTR + r] = kv.w;
            float4 vv = *(const float4*)(g_v + gofs);
            *(float4*)&Vs[r*SSTR + d4] = vv;
        }
        __syncthreads();

        // S = Q K^T  (4x4 per thread)
        float s[4][4];
        #pragma unroll
        for (int i = 0; i < 4; i++)
            #pragma unroll
            for (int j = 0; j < 4; j++) s[i][j] = 0.f;

        #pragma unroll 16
        for (int d = 0; d < 64; d++) {
            float a[4], kk[4];
            *(float4*)a  = *(const float4*)&Qs[d*SSTR + ty*4];
            *(float4*)kk = *(const float4*)&Ks[d*SSTR + tx*4];
            #pragma unroll
            for (int i = 0; i < 4; i++)
                #pragma unroll
                for (int j = 0; j < 4; j++)
                    s[i][j] = fmaf(a[i], kk[j], s[i][j]);
        }

        // causal mask only on the diagonal tile
        if (kt == qt) {
            #pragma unroll
            for (int i = 0; i < 4; i++)
                #pragma unroll
                for (int j = 0; j < 4; j++)
                    if (kbase + tx*4 + j > qbase + ty*4 + i) s[i][j] = -INFINITY;
        }

        // online softmax update + stage P to smem ([c][r])
        #pragma unroll
        for (int i = 0; i < 4; i++) {
            float rm = fmaxf(fmaxf(s[i][0], s[i][1]), fmaxf(s[i][2], s[i][3]));
            #pragma unroll
            for (int off = 8; off > 0; off >>= 1)
                rm = fmaxf(rm, __shfl_xor_sync(0xffffffffu, rm, off, 16));
            float newm = fmaxf(m[i], rm);
            float corr = __expf(m[i] - newm);   // first tile: exp(-inf - finite) = 0
            float rs = 0.f;
            #pragma unroll
            for (int j = 0; j < 4; j++) {
                float p = __expf(s[i][j] - newm);
                s[i][j] = p;
                rs += p;
            }
            #pragma unroll
            for (int off = 8; off > 0; off >>= 1)
                rs += __shfl_xor_sync(0xffffffffu, rs, off, 16);
            l[i] = l[i] * corr + rs;
            m[i] = newm;
            #pragma unroll
            for (int j = 0; j < 4; j++) {
                o[i][j] *= corr;
                Ps[(tx*4 + j)*SSTR + ty*4 + i] = s[i][j];
            }
        }
        __syncthreads();

        // O += P V
        #pragma unroll 16
        for (int c = 0; c < 64; c++) {
            float a[4], vv[4];
            *(float4*)a  = *(const float4*)&Ps[c*SSTR + ty*4];
            *(float4*)vv = *(const float4*)&Vs[c*SSTR + tx*4];
            #pragma unroll
            for (int i = 0; i < 4; i++)
                #pragma unroll
                for (int j = 0; j < 4; j++)
                    o[i][j] = fmaf(a[i], vv[j], o[i][j]);
        }
    }

    // normalize and write ctx in (B,T,D) layout
    #pragma unroll
    for (int i = 0; i < 4; i++) {
        float inv = 1.f / l[i];
        float4 st = { o[i][0]*inv, o[i][1]*inv, o[i][2]*inv, o[i][3]*inv };
        *(float4*)(g_ctx + (size_t)(b*TT + qbase + ty*4 + i)*DD + h*DH + tx*4) = st;
    }
}

// ---------------------------------------------------------------------------
extern "C" void kernel_launch(void* const* d_in, const int* in_sizes, int n_in,
                              void* d_out, int out_size)
{
    (void)in_sizes; (void)n_in; (void)out_size;
    const float* x  = (const float*)d_in[0];
    const float* Wq = (const float*)d_in[1];
    const float* bq = (const float*)d_in[2];
    const float* Wk = (const float*)d_in[3];
    const float* bk = (const float*)d_in[4];
    const float* Wv = (const float*)d_in[5];
    const float* bv = (const float*)d_in[6];
    const float* Wo = (const float*)d_in[7];
    const float* bo = (const float*)d_in[8];
    float* out = (float*)d_out;

    float *q, *k, *v, *ctx;
    cudaGetSymbolAddress((void**)&q,   g_q);
    cudaGetSymbolAddress((void**)&k,   g_k);
    cudaGetSymbolAddress((void**)&v,   g_v);
    cudaGetSymbolAddress((void**)&ctx, g_ctx);

    const int attn_smem = 4 * 64 * SSTR * (int)sizeof(float);  // 69632 B
    cudaFuncSetAttribute(flash_attn_kernel,
                         cudaFuncAttributeMaxDynamicSharedMemorySize, attn_smem);

    dim3 gthr(256);
    dim3 ggrid(DD/128, NTOK/128);          // (8, 32)
    gemm_bias_kernel<<<ggrid, gthr>>>(x, Wq, bq, q, NTOK, DD, DD);
    gemm_bias_kernel<<<ggrid, gthr>>>(x, Wk, bk, k, NTOK, DD, DD);
    gemm_bias_kernel<<<ggrid, gthr>>>(x, Wv, bv, v, NTOK, DD, DD);

    dim3 agrid(TT/64, HH, BB);             // (32, 16, 2)
    flash_attn_kernel<<<agrid, 256, attn_smem>>>();

    gemm_bias_kernel<<<ggrid, gthr>>>(ctx, Wo, bo, out, NTOK, DD, DD);
}

// round 3
// speedup vs baseline: 1.3924x; 1.3924x over previous
#include <cuda_runtime.h>
#include <cuda_bf16.h>
#include <math.h>
#include <stdint.h>

#define BB 2
#define TT 2048
#define DD 1024
#define HH 16
#define DH 64
#define NTOK (BB*TT)
#define KX 3072                 // expanded K for bf16x3
#define NCH 96                  // 3072 / 32 K-chunks
#define NST 4                   // pipeline stages
#define ROWB 80                 // padded smem row stride in bytes (40 bf16)
#define STAGE_B (128*ROWB*2)    // A half + B half = 20480 B
#define A_HALF  (128*ROWB)      // 10240 B
#define GEMM_SMEM (NST*STAGE_B) // 81920 B

// Scratch (allocation forbidden; __device__ globals are the sanctioned path)
__device__ float g_q[NTOK*DD];
__device__ float g_k[NTOK*DD];
__device__ float g_v[NTOK*DD];
__device__ float g_ctx[NTOK*DD];
__device__ __nv_bfloat16 g_abuf[(size_t)NTOK*KX];   // x split    [4096][3072]
__device__ __nv_bfloat16 g_cbuf[(size_t)NTOK*KX];   // ctx split  [4096][3072]
__device__ __nv_bfloat16 g_wbuf[(size_t)3*DD*KX];   // Wq|Wk|Wv   [3072][3072]
__device__ __nv_bfloat16 g_wobuf[(size_t)DD*KX];    // Wo         [1024][3072]

// ---------------------------------------------------------------------------
// PTX helpers (base-ISA only: cp.async, ldmatrix, mma.sync — no tcgen05)
// ---------------------------------------------------------------------------
__device__ __forceinline__ uint32_t smem_u32(const void* p) {
    uint32_t a;
    asm("{ .reg .u64 t; cvta.to.shared.u64 t, %1; cvt.u32.u64 %0, t; }" : "=r"(a) : "l"(p));
    return a;
}
__device__ __forceinline__ void cpasync16(uint32_t saddr, const void* gaddr) {
    asm volatile("cp.async.cg.shared.global [%0], [%1], 16;" :: "r"(saddr), "l"(gaddr) : "memory");
}
__device__ __forceinline__ void cp_commit() { asm volatile("cp.async.commit_group;" ::: "memory"); }
__device__ __forceinline__ void cp_wait2()  { asm volatile("cp.async.wait_group 2;"  ::: "memory"); }

__device__ __forceinline__ void ldmx4(uint32_t* r, uint32_t addr) {
    asm volatile("ldmatrix.sync.aligned.m8n8.x4.shared.b16 {%0,%1,%2,%3}, [%4];"
                 : "=r"(r[0]), "=r"(r[1]), "=r"(r[2]), "=r"(r[3]) : "r"(addr));
}
__device__ __forceinline__ void mma16816(float* c, const uint32_t* a, uint32_t b0, uint32_t b1) {
    asm volatile(
        "mma.sync.aligned.m16n8k16.row.col.f32.bf16.bf16.f32 "
        "{%0,%1,%2,%3}, {%4,%5,%6,%7}, {%8,%9}, {%0,%1,%2,%3};"
        : "+f"(c[0]), "+f"(c[1]), "+f"(c[2]), "+f"(c[3])
        : "r"(a[0]), "r"(a[1]), "r"(a[2]), "r"(a[3]), "r"(b0), "r"(b1));
}

// ---------------------------------------------------------------------------
// fp32 -> bf16x3 split. mode 0 (activations): [hi | lo | hi]
//                       mode 1 (weights):     [hi | hi | lo]
// products summed: hi*hi + lo*hi + hi*lo  (lo*lo ~ 2^-18, dropped)
// ---------------------------------------------------------------------------
__global__ void prep_triple(const float* __restrict__ src, __nv_bfloat16* __restrict__ dst,
                            int n, int mode)
{
    int i = blockIdx.x * 256 + threadIdx.x;
    if (i >= n) return;
    int r = i >> 10, c = i & 1023;
    float v = src[i];
    __nv_bfloat16 hi = __float2bfloat16(v);
    __nv_bfloat16 lo = __float2bfloat16(v - __bfloat162float(hi));
    size_t base = (size_t)r * KX + c;
    dst[base]        = hi;
    dst[base + 1024] = mode ? hi : lo;
    dst[base + 2048] = mode ? lo : hi;
}

// ---------------------------------------------------------------------------
// HMMA GEMM: C[4096,1024] = A'[4096,3072](bf16) @ W'[1024,3072](bf16)^T + bias
// CTA: 128x128, 8 warps (2Mx4N), warp tile 64x32, BK=32, 4-stage cp.async.
// smem rows padded to 80B -> ldmatrix conflict-free without swizzle.
// grid = (N/128, M/128, z)
// ---------------------------------------------------------------------------
__device__ __forceinline__ void load_chunk(uint32_t stage_base,
    const __nv_bfloat16* __restrict__ A, const __nv_bfloat16* __restrict__ Wz,
    int mBase, int nBase, int chunk, int tid)
{
    const __nv_bfloat16* Ab = A  + (size_t)mBase * KX + chunk * 32;
    const __nv_bfloat16* Bb = Wz + (size_t)nBase * KX + chunk * 32;
    #pragma unroll
    for (int j = 0; j < 2; j++) {          // A: 128 rows x 4 granules(16B)
        int idx = tid + j * 256;
        int row = idx >> 2, g = idx & 3;
        cpasync16(stage_base + row * ROWB + g * 16, Ab + (size_t)row * KX + g * 8);
    }
    #pragma unroll
    for (int j = 0; j < 2; j++) {          // B: 128 rows x 4 granules
        int idx = tid + j * 256;
        int row = idx >> 2, g = idx & 3;
        cpasync16(stage_base + A_HALF + row * ROWB + g * 16, Bb + (size_t)row * KX + g * 8);
    }
}

__global__ __launch_bounds__(256, 2) void mma_gemm(
    const __nv_bfloat16* __restrict__ A, const __nv_bfloat16* __restrict__ W,
    const float* b0p, const float* b1p, const float* b2p,
    float* o0, float* o1, float* o2)
{
    extern __shared__ char sm_raw[];
    const uint32_t smem = smem_u32(sm_raw);

    const int tid = threadIdx.x;
    const int wid = tid >> 5, lid = tid & 31;
    const int warpM = wid >> 2;            // 0..1 -> 64-row slab
    const int warpN = wid & 3;             // 0..3 -> 32-col slab
    const int nBase = blockIdx.x * 128;
    const int mBase = blockIdx.y * 128;
    const int z = blockIdx.z;
    const __nv_bfloat16* Wz = W + (size_t)z * DD * KX;
    const float* bias = (z == 0) ? b0p : (z == 1) ? b1p : b2p;
    float* outp       = (z == 0) ? o0  : (z == 1) ? o1  : o2;

    float acc[4][4][4];
    #pragma unroll
    for (int mi = 0; mi < 4; mi++)
        #pragma unroll
        for (int nj = 0; nj < 4; nj++)
            #pragma unroll
            for (int e = 0; e < 4; e++) acc[mi][nj][e] = 0.f;

    // lane-constant ldmatrix offsets
    const uint32_t aOff = (uint32_t)(warpM * 64 + (lid & 15)) * ROWB + ((lid >> 4) << 4);
    const uint32_t bOff = A_HALF +
        (uint32_t)(warpN * 32 + (lid & 7) + ((lid >> 4) << 3)) * ROWB + (((lid >> 3) & 1) << 4);

    // prologue: fill 3 stages
    #pragma unroll
    for (int s = 0; s < NST - 1; s++) {
        load_chunk(smem + s * STAGE_B, A, Wz, mBase, nBase, s, tid);
        cp_commit();
    }

    for (int i = 0; i < NCH; i++) {
        const uint32_t st = smem + (i & (NST - 1)) * STAGE_B;
        cp_wait2();
        __syncthreads();                    // chunk i visible; slot (i+3)&3 free

        int nxt = i + NST - 1;
        if (nxt < NCH) {
            load_chunk(smem + (nxt & (NST - 1)) * STAGE_B, A, Wz, mBase, nBase, nxt, tid);
            cp_commit();
        }

        #pragma unroll
        for (int kp = 0; kp < 2; kp++) {
            const uint32_t kOff = kp * 32;  // 16 bf16 = 32 B
            uint32_t af[4][4], bf[2][4];
            #pragma unroll
            for (int mi = 0; mi < 4; mi++)
                ldmx4(af[mi], st + aOff + mi * (16 * ROWB) + kOff);
            #pragma unroll
            for (int g = 0; g < 2; g++)
                ldmx4(bf[g], st + bOff + g * (16 * ROWB) + kOff);
            #pragma unroll
            for (int mi = 0; mi < 4; mi++)
                #pragma unroll
                for (int nj = 0; nj < 4; nj++)
                    mma16816(acc[mi][nj], af[mi], bf[nj >> 1][(nj & 1) * 2], bf[nj >> 1][(nj & 1) * 2 + 1]);
        }
    }

    // epilogue: bias add, direct store
    const int rBase = mBase + warpM * 64 + (lid >> 2);
    const int cBase = nBase + warpN * 32 + (lid & 3) * 2;
    #pragma unroll
    for (int mi = 0; mi < 4; mi++) {
        #pragma unroll
        for (int nj = 0; nj < 4; nj++) {
            int col = cBase + nj * 8;
            float bx = bias[col], by = bias[col + 1];
            int r0 = rBase + mi * 16;
            float2 v0 = { acc[mi][nj][0] + bx, acc[mi][nj][1] + by };
            float2 v1 = { acc[mi][nj][2] + bx, acc[mi][nj][3] + by };
            *(float2*)(outp + (size_t)r0 * DD + col)       = v0;
            *(float2*)(outp + (size_t)(r0 + 8) * DD + col) = v1;
        }
    }
}

// ---------------------------------------------------------------------------
// Flash attention (unchanged: causal, fp32, head_dim=64)
// ---------------------------------------------------------------------------
#define SSTR 68

__global__ __launch_bounds__(256) void flash_attn_kernel()
{
    extern __shared__ float sm[];
    float* Qs = sm;
    float* Ks = sm + 64*SSTR;
    float* Vs = sm + 2*64*SSTR;
    float* Ps = sm + 3*64*SSTR;

    const int tid = threadIdx.x;
    const int tx  = tid & 15;
    const int ty  = tid >> 4;
    const int qt = gridDim.x - 1 - blockIdx.x;
    const int h  = blockIdx.y;
    const int b  = blockIdx.z;
    const int qbase = qt * 64;

    #pragma unroll
    for (int i = 0; i < 4; i++) {
        int f  = tid + i*256;
        int r  = f >> 4;
        int d4 = (f & 15) << 2;
        float4 v = *(const float4*)(g_q + (size_t)(b*TT + qbase + r)*DD + h*DH + d4);
        Qs[(d4+0)*SSTR + r] = v.x * 0.125f;
        Qs[(d4+1)*SSTR + r] = v.y * 0.125f;
        Qs[(d4+2)*SSTR + r] = v.z * 0.125f;
        Qs[(d4+3)*SSTR + r] = v.w * 0.125f;
    }

    float m[4], l[4], o[4][4];
    #pragma unroll
    for (int i = 0; i < 4; i++) {
        m[i] = -INFINITY; l[i] = 0.f;
        #pragma unroll
        for (int j = 0; j < 4; j++) o[i][j] = 0.f;
    }

    for (int kt = 0; kt <= qt; kt++) {
        const int kbase = kt * 64;
        __syncthreads();

        #pragma unroll
        for (int i = 0; i < 4; i++) {
            int f  = tid + i*256;
            int r  = f >> 4;
            int d4 = (f & 15) << 2;
            size_t gofs = (size_t)(b*TT + kbase + r)*DD + h*DH + d4;
            float4 kv = *(const float4*)(g_k + gofs);
            Ks[(d4+0)*SSTR + r] = kv.x;
            Ks[(d4+1)*SSTR + r] = kv.y;
            Ks[(d4+2)*SSTR + r] = kv.z;
            Ks[(d4+3)*SSTR + r] = kv.w;
            float4 vv = *(const float4*)(g_v + gofs);
            *(float4*)&Vs[r*SSTR + d4] = vv;
        }
        __syncthreads();

        float s[4][4];
        #pragma unroll
        for (int i = 0; i < 4; i++)
            #pragma unroll
            for (int j = 0; j < 4; j++) s[i][j] = 0.f;

        #pragma unroll 16
        for (int d = 0; d < 64; d++) {
            float a[4], kk[4];
            *(float4*)a  = *(const float4*)&Qs[d*SSTR + ty*4];
            *(float4*)kk = *(const float4*)&Ks[d*SSTR + tx*4];
            #pragma unroll
            for (int i = 0; i < 4; i++)
                #pragma unroll
                for (int j = 0; j < 4; j++)
                    s[i][j] = fmaf(a[i], kk[j], s[i][j]);
        }

        if (kt == qt) {
            #pragma unroll
            for (int i = 0; i < 4; i++)
                #pragma unroll
                for (int j = 0; j < 4; j++)
                    if (kbase + tx*4 + j > qbase + ty*4 + i) s[i][j] = -INFINITY;
        }

        #pragma unroll
        for (int i = 0; i < 4; i++) {
            float rm = fmaxf(fmaxf(s[i][0], s[i][1]), fmaxf(s[i][2], s[i][3]));
            #pragma unroll
            for (int off = 8; off > 0; off >>= 1)
                rm = fmaxf(rm, __shfl_xor_sync(0xffffffffu, rm, off, 16));
            float newm = fmaxf(m[i], rm);
            float corr = __expf(m[i] - newm);
            float rs = 0.f;
            #pragma unroll
            for (int j = 0; j < 4; j++) {
                float p = __expf(s[i][j] - newm);
                s[i][j] = p;
                rs += p;
            }
            #pragma unroll
            for (int off = 8; off > 0; off >>= 1)
                rs += __shfl_xor_sync(0xffffffffu, rs, off, 16);
            l[i] = l[i] * corr + rs;
            m[i] = newm;
            #pragma unroll
            for (int j = 0; j < 4; j++) {
                o[i][j] *= corr;
                Ps[(tx*4 + j)*SSTR + ty*4 + i] = s[i][j];
            }
        }
        __syncthreads();

        #pragma unroll 16
        for (int c = 0; c < 64; c++) {
            float a[4], vv[4];
            *(float4*)a  = *(const float4*)&Ps[c*SSTR + ty*4];
            *(float4*)vv = *(const float4*)&Vs[c*SSTR + tx*4];
            #pragma unroll
            for (int i = 0; i < 4; i++)
                #pragma unroll
                for (int j = 0; j < 4; j++)
                    o[i][j] = fmaf(a[i], vv[j], o[i][j]);
        }
    }

    #pragma unroll
    for (int i = 0; i < 4; i++) {
        float inv = 1.f / l[i];
        float4 st = { o[i][0]*inv, o[i][1]*inv, o[i][2]*inv, o[i][3]*inv };
        *(float4*)(g_ctx + (size_t)(b*TT + qbase + ty*4 + i)*DD + h*DH + tx*4) = st;
    }
}

// ---------------------------------------------------------------------------
extern "C" void kernel_launch(void* const* d_in, const int* in_sizes, int n_in,
                              void* d_out, int out_size)
{
    (void)in_sizes; (void)n_in; (void)out_size;
    const float* x  = (const float*)d_in[0];
    const float* Wq = (const float*)d_in[1];
    const float* bq = (const float*)d_in[2];
    const float* Wk = (const float*)d_in[3];
    const float* bk = (const float*)d_in[4];
    const float* Wv = (const float*)d_in[5];
    const float* bv = (const float*)d_in[6];
    const float* Wo = (const float*)d_in[7];
    const float* bo = (const float*)d_in[8];
    float* out = (float*)d_out;

    float *q, *k, *v, *ctx;
    __nv_bfloat16 *abuf, *cbuf, *wbuf, *wobuf;
    cudaGetSymbolAddress((void**)&q,     g_q);
    cudaGetSymbolAddress((void**)&k,     g_k);
    cudaGetSymbolAddress((void**)&v,     g_v);
    cudaGetSymbolAddress((void**)&ctx,   g_ctx);
    cudaGetSymbolAddress((void**)&abuf,  g_abuf);
    cudaGetSymbolAddress((void**)&cbuf,  g_cbuf);
    cudaGetSymbolAddress((void**)&wbuf,  g_wbuf);
    cudaGetSymbolAddress((void**)&wobuf, g_wobuf);

    const int attn_smem = 4 * 64 * SSTR * (int)sizeof(float);
    cudaFuncSetAttribute(flash_attn_kernel,
                         cudaFuncAttributeMaxDynamicSharedMemorySize, attn_smem);
    cudaFuncSetAttribute(mma_gemm,
                         cudaFuncAttributeMaxDynamicSharedMemorySize, GEMM_SMEM);

    // split inputs to bf16x3
    prep_triple<<<NTOK*DD/256, 256>>>(x,  abuf, NTOK*DD, 0);
    prep_triple<<<DD*DD/256,  256>>>(Wq, wbuf,                   DD*DD, 1);
    prep_triple<<<DD*DD/256,  256>>>(Wk, wbuf + (size_t)DD*KX,   DD*DD, 1);
    prep_triple<<<DD*DD/256,  256>>>(Wv, wbuf + (size_t)2*DD*KX, DD*DD, 1);
    prep_triple<<<DD*DD/256,  256>>>(Wo, wobuf,                  DD*DD, 1);

    // fused QKV projections (HMMA tensor cores)
    mma_gemm<<<dim3(DD/128, NTOK/128, 3), 256, GEMM_SMEM>>>(
        abuf, wbuf, bq, bk, bv, q, k, v);

    // attention
    dim3 agrid(TT/64, HH, BB);
    flash_attn_kernel<<<agrid, 256, attn_smem>>>();

    // output projection
    prep_triple<<<NTOK*DD/256, 256>>>(ctx, cbuf, NTOK*DD, 0);
    mma_gemm<<<dim3(DD/128, NTOK/128, 1), 256, GEMM_SMEM>>>(
        cbuf, wobuf, bo, bo, bo, out, out, out);
}

// round 4
// speedup vs baseline: 3.0623x; 2.1993x over previous
#include <cuda_runtime.h>
#include <cuda_fp16.h>
#include <cuda_bf16.h>
#include <math.h>
#include <stdint.h>

#define BB 2
#define TT 2048
#define DD 1024
#define HH 16
#define DH 64
#define NTOK (BB*TT)
#define KX 3072                 // expanded K for bf16x3
#define NCH 96                  // 3072 / 32 K-chunks
#define NST 4                   // gemm pipeline stages
#define ROWB 80                 // gemm smem row stride bytes
#define STAGE_B (128*ROWB*2)
#define A_HALF  (128*ROWB)
#define GEMM_SMEM (NST*STAGE_B)
#define QSCALE 0.1803368801f    // log2(e) / sqrt(64)

// flash smem geometry: rows padded to 72 halves (144B) -> conflict-free ldmatrix
#define FROW 144
#define FSTG_K 9216             // 64*144 (K tile)
#define FSTG   18432            // K + V per stage
#define FSMEM  36864            // 2 stages (Q staged through stage region first)

// Scratch (allocation forbidden; __device__ globals are the sanctioned path)
__device__ float g_ctx[NTOK*DD];
__device__ __half g_qh[NTOK*DD];                    // pre-scaled by QSCALE
__device__ __half g_kh[NTOK*DD];
__device__ __half g_vh[NTOK*DD];
__device__ __nv_bfloat16 g_abuf[(size_t)NTOK*KX];
__device__ __nv_bfloat16 g_cbuf[(size_t)NTOK*KX];
__device__ __nv_bfloat16 g_wbuf[(size_t)3*DD*KX];
__device__ __nv_bfloat16 g_wobuf[(size_t)DD*KX];

// ---------------------------------------------------------------------------
// PTX helpers (base ISA: cp.async, ldmatrix, mma.sync)
// ---------------------------------------------------------------------------
__device__ __forceinline__ uint32_t smem_u32(const void* p) {
    uint32_t a;
    asm("{ .reg .u64 t; cvta.to.shared.u64 t, %1; cvt.u32.u64 %0, t; }" : "=r"(a) : "l"(p));
    return a;
}
__device__ __forceinline__ void cpasync16(uint32_t saddr, const void* gaddr) {
    asm volatile("cp.async.cg.shared.global [%0], [%1], 16;" :: "r"(saddr), "l"(gaddr) : "memory");
}
__device__ __forceinline__ void cp_commit() { asm volatile("cp.async.commit_group;" ::: "memory"); }
__device__ __forceinline__ void cp_wait0()  { asm volatile("cp.async.wait_group 0;" ::: "memory"); }
__device__ __forceinline__ void cp_wait1()  { asm volatile("cp.async.wait_group 1;" ::: "memory"); }
__device__ __forceinline__ void cp_wait2()  { asm volatile("cp.async.wait_group 2;" ::: "memory"); }

__device__ __forceinline__ void ldmx4(uint32_t* r, uint32_t addr) {
    asm volatile("ldmatrix.sync.aligned.m8n8.x4.shared.b16 {%0,%1,%2,%3}, [%4];"
                 : "=r"(r[0]), "=r"(r[1]), "=r"(r[2]), "=r"(r[3]) : "r"(addr));
}
__device__ __forceinline__ void ldmx4t(uint32_t* r, uint32_t addr) {
    asm volatile("ldmatrix.sync.aligned.m8n8.x4.trans.shared.b16 {%0,%1,%2,%3}, [%4];"
                 : "=r"(r[0]), "=r"(r[1]), "=r"(r[2]), "=r"(r[3]) : "r"(addr));
}
__device__ __forceinline__ void ldmx2t(uint32_t* r, uint32_t addr) {
    asm volatile("ldmatrix.sync.aligned.m8n8.x2.trans.shared.b16 {%0,%1}, [%2];"
                 : "=r"(r[0]), "=r"(r[1]) : "r"(addr));
}
__device__ __forceinline__ void mma_bf16(float* c, const uint32_t* a, uint32_t b0, uint32_t b1) {
    asm volatile(
        "mma.sync.aligned.m16n8k16.row.col.f32.bf16.bf16.f32 "
        "{%0,%1,%2,%3}, {%4,%5,%6,%7}, {%8,%9}, {%0,%1,%2,%3};"
        : "+f"(c[0]), "+f"(c[1]), "+f"(c[2]), "+f"(c[3])
        : "r"(a[0]), "r"(a[1]), "r"(a[2]), "r"(a[3]), "r"(b0), "r"(b1));
}
__device__ __forceinline__ void mma_fp16(float* c, const uint32_t* a, uint32_t b0, uint32_t b1) {
    asm volatile(
        "mma.sync.aligned.m16n8k16.row.col.f32.f16.f16.f32 "
        "{%0,%1,%2,%3}, {%4,%5,%6,%7}, {%8,%9}, {%0,%1,%2,%3};"
        : "+f"(c[0]), "+f"(c[1]), "+f"(c[2]), "+f"(c[3])
        : "r"(a[0]), "r"(a[1]), "r"(a[2]), "r"(a[3]), "r"(b0), "r"(b1));
}
// pack two f32 into f16x2: lo -> low half
__device__ __forceinline__ uint32_t packh2(float lo, float hi) {
    uint32_t u;
    asm("cvt.rn.f16x2.f32 %0, %1, %2;" : "=r"(u) : "f"(hi), "f"(lo));
    return u;
}
// exp2 via deg-3 poly on the FMA pipe (masked inputs are -60, no clamp needed)
__device__ __forceinline__ float exp2_poly(float y) {
    float t = y + 12582912.f;            // magic 1.5*2^23
    float n = t - 12582912.f;
    float f = y - n;
    float p = fmaf(0.0555041f, f, 0.2440313f);
    p = fmaf(p, f, 0.6931472f);
    p = fmaf(p, f, 0.9999252f);
    return __int_as_float(__float_as_int(p) + (__float_as_int(t) << 23));
}
__device__ __forceinline__ float exp2_mufu(float y) {
    float r;
    asm("ex2.approx.f32 %0, %1;" : "=f"(r) : "f"(y));
    return r;
}

// ---------------------------------------------------------------------------
// fp32 -> bf16x3 split. mode 0 (activations): [hi | lo | hi]
//                       mode 1 (weights):     [hi | hi | lo]
// ---------------------------------------------------------------------------
__global__ void prep_triple(const float* __restrict__ src, __nv_bfloat16* __restrict__ dst,
                            int n, int mode)
{
    int i = blockIdx.x * 256 + threadIdx.x;
    if (i >= n) return;
    int r = i >> 10, c = i & 1023;
    float v = src[i];
    __nv_bfloat16 hi = __float2bfloat16(v);
    __nv_bfloat16 lo = __float2bfloat16(v - __bfloat162float(hi));
    size_t base = (size_t)r * KX + c;
    dst[base]        = hi;
    dst[base + 1024] = mode ? hi : lo;
    dst[base + 2048] = mode ? lo : hi;
}

// ---------------------------------------------------------------------------
// HMMA GEMM (bf16x3): C[4096,1024] = A' @ W'^T + bias.
// half_out=1: writes fp16 (Q scaled by QSCALE). half_out=0: fp32.
// ---------------------------------------------------------------------------
__device__ __forceinline__ void load_chunk(uint32_t stage_base,
    const __nv_bfloat16* __restrict__ A, const __nv_bfloat16* __restrict__ Wz,
    int mBase, int nBase, int chunk, int tid)
{
    const __nv_bfloat16* Ab = A  + (size_t)mBase * KX + chunk * 32;
    const __nv_bfloat16* Bb = Wz + (size_t)nBase * KX + chunk * 32;
    #pragma unroll
    for (int j = 0; j < 2; j++) {
        int idx = tid + j * 256;
        int row = idx >> 2, g = idx & 3;
        cpasync16(stage_base + row * ROWB + g * 16, Ab + (size_t)row * KX + g * 8);
    }
    #pragma unroll
    for (int j = 0; j < 2; j++) {
        int idx = tid + j * 256;
        int row = idx >> 2, g = idx & 3;
        cpasync16(stage_base + A_HALF + row * ROWB + g * 16, Bb + (size_t)row * KX + g * 8);
    }
}

__global__ __launch_bounds__(256, 2) void mma_gemm(
    const __nv_bfloat16* __restrict__ A, const __nv_bfloat16* __restrict__ W,
    const float* b0p, const float* b1p, const float* b2p,
    float* o0, __half* h0, __half* h1, __half* h2, int half_out)
{
    extern __shared__ char sm_raw[];
    const uint32_t smem = smem_u32(sm_raw);

    const int tid = threadIdx.x;
    const int wid = tid >> 5, lid = tid & 31;
    const int warpM = wid >> 2;
    const int warpN = wid & 3;
    const int nBase = blockIdx.x * 128;
    const int mBase = blockIdx.y * 128;
    const int z = blockIdx.z;
    const __nv_bfloat16* Wz = W + (size_t)z * DD * KX;
    const float* bias = (z == 0) ? b0p : (z == 1) ? b1p : b2p;

    float acc[4][4][4];
    #pragma unroll
    for (int mi = 0; mi < 4; mi++)
        #pragma unroll
        for (int nj = 0; nj < 4; nj++)
            #pragma unroll
            for (int e = 0; e < 4; e++) acc[mi][nj][e] = 0.f;

    const uint32_t aOff = (uint32_t)(warpM * 64 + (lid & 15)) * ROWB + ((lid >> 4) << 4);
    const uint32_t bOff = A_HALF +
        (uint32_t)(warpN * 32 + (lid & 7) + ((lid >> 4) << 3)) * ROWB + (((lid >> 3) & 1) << 4);

    #pragma unroll
    for (int s = 0; s < NST - 1; s++) {
        load_chunk(smem + s * STAGE_B, A, Wz, mBase, nBase, s, tid);
        cp_commit();
    }

    for (int i = 0; i < NCH; i++) {
        const uint32_t st = smem + (i & (NST - 1)) * STAGE_B;
        cp_wait2();
        __syncthreads();

        int nxt = i + NST - 1;
        if (nxt < NCH) {
            load_chunk(smem + (nxt & (NST - 1)) * STAGE_B, A, Wz, mBase, nBase, nxt, tid);
            cp_commit();
        }

        #pragma unroll
        for (int kp = 0; kp < 2; kp++) {
            const uint32_t kOff = kp * 32;
            uint32_t af[4][4], bf[2][4];
            #pragma unroll
            for (int mi = 0; mi < 4; mi++)
                ldmx4(af[mi], st + aOff + mi * (16 * ROWB) + kOff);
            #pragma unroll
            for (int g = 0; g < 2; g++)
                ldmx4(bf[g], st + bOff + g * (16 * ROWB) + kOff);
            #pragma unroll
            for (int mi = 0; mi < 4; mi++)
                #pragma unroll
                for (int nj = 0; nj < 4; nj++)
                    mma_bf16(acc[mi][nj], af[mi], bf[nj >> 1][(nj & 1) * 2], bf[nj >> 1][(nj & 1) * 2 + 1]);
        }
    }

    const int rBase = mBase + warpM * 64 + (lid >> 2);
    const int cBase = nBase + warpN * 32 + (lid & 3) * 2;
    if (half_out) {
        __half* hp = (z == 0) ? h0 : (z == 1) ? h1 : h2;
        const float sc = (z == 0) ? QSCALE : 1.f;
        #pragma unroll
        for (int mi = 0; mi < 4; mi++) {
            #pragma unroll
            for (int nj = 0; nj < 4; nj++) {
                int col = cBase + nj * 8;
                float bx = bias[col], by = bias[col + 1];
                int r0 = rBase + mi * 16;
                __half2 v0 = __floats2half2_rn((acc[mi][nj][0] + bx) * sc, (acc[mi][nj][1] + by) * sc);
                __half2 v1 = __floats2half2_rn((acc[mi][nj][2] + bx) * sc, (acc[mi][nj][3] + by) * sc);
                *(__half2*)(hp + (size_t)r0 * DD + col)       = v0;
                *(__half2*)(hp + (size_t)(r0 + 8) * DD + col) = v1;
            }
        }
    } else {
        #pragma unroll
        for (int mi = 0; mi < 4; mi++) {
            #pragma unroll
            for (int nj = 0; nj < 4; nj++) {
                int col = cBase + nj * 8;
                float bx = bias[col], by = bias[col + 1];
                int r0 = rBase + mi * 16;
                float2 v0 = { acc[mi][nj][0] + bx, acc[mi][nj][1] + by };
                float2 v1 = { acc[mi][nj][2] + bx, acc[mi][nj][3] + by };
                *(float2*)(o0 + (size_t)r0 * DD + col)       = v0;
                *(float2*)(o0 + (size_t)(r0 + 8) * DD + col) = v1;
            }
        }
    }
}

// ---------------------------------------------------------------------------
// Tensorized causal flash attention, head_dim=64, fp16 mma, no-max softmax.
// CTA: 128 q-rows x (b,h). 8 warps x 16 rows. K/V tiles of 64 keys,
// 2-stage cp.async. Scores arrive in log2 domain (Q pre-scaled).
// Row sums via a ones-column block appended to V (n-tile 8).
// ---------------------------------------------------------------------------
__global__ __launch_bounds__(256) void flash_mma()
{
    __shared__ __align__(1024) char sm_f[FSMEM];
    const uint32_t base = smem_u32(sm_f);

    const int tid = threadIdx.x;
    const int wid = tid >> 5, lid = tid & 31;
    const int qt = 15 - blockIdx.x;            // reverse order: heavy tiles first
    const int h  = blockIdx.y;
    const int b  = blockIdx.z;
    const int qb = qt * 128;
    const int nk = (qt + 1) * 2;               // 64-key tiles

    const __half* qp = g_qh + (size_t)(b * TT + qb) * DD + h * DH;
    const __half* kp0 = g_kh + (size_t)(b * TT) * DD + h * DH;
    const __half* vp0 = g_vh + (size_t)(b * TT) * DD + h * DH;

    // ---- stage Q (128 x 64 fp16) through smem, load A-frags ----
    #pragma unroll
    for (int j = 0; j < 4; j++) {
        int idx = tid + j * 256;
        int row = idx >> 3, g = idx & 7;
        cpasync16(base + row * FROW + g * 16, qp + (size_t)row * DD + g * 8);
    }
    cp_commit(); cp_wait0();
    __syncthreads();
    uint32_t qf[4][4];
    const uint32_t qaddr = base + (uint32_t)(wid * 16 + (lid & 15)) * FROW + ((lid >> 4) << 4);
    #pragma unroll
    for (int ks = 0; ks < 4; ks++) ldmx4(qf[ks], qaddr + ks * 32);
    __syncthreads();                            // Q region now reusable

    // ones columns for both V stages (bytes 128..143 of each V row)
    if (tid < 128) {
        int s = tid >> 6, r = tid & 63;
        uint4 ones = { 0x3C003C00u, 0x3C003C00u, 0x3C003C00u, 0x3C003C00u };
        *(uint4*)(sm_f + s * FSTG + FSTG_K + r * FROW + 128) = ones;
    }

    // ---- preload ktile 0 ----
    {
        #pragma unroll
        for (int j = 0; j < 2; j++) {
            int idx = tid + j * 256;
            int row = idx >> 3, g = idx & 7;
            cpasync16(base + row * FROW + g * 16,          kp0 + (size_t)row * DD + g * 8);
            cpasync16(base + FSTG_K + row * FROW + g * 16, vp0 + (size_t)row * DD + g * 8);
        }
        cp_commit();
    }

    float of[9][4];
    #pragma unroll
    for (int t = 0; t < 9; t++)
        #pragma unroll
        for (int e = 0; e < 4; e++) of[t][e] = 0.f;

    const uint32_t kfOff = (uint32_t)((lid & 7) + ((lid >> 4) << 3)) * FROW + (((lid >> 3) & 1) << 4);
    const uint32_t vfOff = (uint32_t)((lid & 7) + (((lid >> 3) & 1) << 3)) * FROW + ((lid >> 4) << 4);
    const uint32_t vsOff = (uint32_t)((lid & 7) + (((lid >> 3) & 1) << 3)) * FROW + 128;

    for (int kt = 0; kt < nk; kt++) {
        const int s = kt & 1;
        const int kb = kt * 64;
        __syncthreads();                        // prior compute done: other stage reusable
        if (kt + 1 < nk) {
            const __half* kp = kp0 + (size_t)(kb + 64) * DD;
            const __half* vp = vp0 + (size_t)(kb + 64) * DD;
            uint32_t sb = base + (s ^ 1) * FSTG;
            #pragma unroll
            for (int j = 0; j < 2; j++) {
                int idx = tid + j * 256;
                int row = idx >> 3, g = idx & 7;
                cpasync16(sb + row * FROW + g * 16,          kp + (size_t)row * DD + g * 8);
                cpasync16(sb + FSTG_K + row * FROW + g * 16, vp + (size_t)row * DD + g * 8);
            }
            cp_commit(); cp_wait1();
        } else {
            cp_wait0();
        }
        __syncthreads();

        const uint32_t st = base + s * FSTG;

        // S = Q K^T (log2 domain), 16x64 per warp
        float sf[8][4];
        #pragma unroll
        for (int t = 0; t < 8; t++)
            #pragma unroll
            for (int e = 0; e < 4; e++) sf[t][e] = 0.f;

        #pragma unroll
        for (int ks = 0; ks < 4; ks++) {
            uint32_t bf[4][4];
            #pragma unroll
            for (int t = 0; t < 4; t++)
                ldmx4(bf[t], st + kfOff + t * (16 * FROW) + ks * 32);
            #pragma unroll
            for (int nt = 0; nt < 8; nt++)
                mma_fp16(sf[nt], qf[ks], bf[nt >> 1][(nt & 1) * 2], bf[nt >> 1][(nt & 1) * 2 + 1]);
        }

        // causal mask (only tiles crossing the diagonal): masked -> -60 (exp2 ~ 0)
        if (kb + 63 > qb) {
            const int r0 = qb + wid * 16 + (lid >> 2);
            const int c0 = kb + 2 * (lid & 3);
            #pragma unroll
            for (int nt = 0; nt < 8; nt++)
                #pragma unroll
                for (int e = 0; e < 4; e++) {
                    int col = c0 + nt * 8 + (e & 1);
                    int row = r0 + (e >> 1) * 8;
                    if (col > row) sf[nt][e] = -60.f;
                }
        }

        // P = exp2(S): ntiles 3,7 on MUFU, rest on FMA-pipe poly
        uint32_t pf[8][2];
        #pragma unroll
        for (int nt = 0; nt < 8; nt++) {
            float p0, p1, p2, p3;
            if ((nt & 3) == 3) {
                p0 = exp2_mufu(sf[nt][0]); p1 = exp2_mufu(sf[nt][1]);
                p2 = exp2_mufu(sf[nt][2]); p3 = exp2_mufu(sf[nt][3]);
            } else {
                p0 = exp2_poly(sf[nt][0]); p1 = exp2_poly(sf[nt][1]);
                p2 = exp2_poly(sf[nt][2]); p3 = exp2_poly(sf[nt][3]);
            }
            pf[nt][0] = packh2(p0, p1);
            pf[nt][1] = packh2(p2, p3);
        }

        // O += P V   (V^T frags via ldmatrix.trans; n-tile 8 = ones -> row sums)
        #pragma unroll
        for (int ks = 0; ks < 4; ks++) {
            uint32_t pa[4] = { pf[2*ks][0], pf[2*ks][1], pf[2*ks+1][0], pf[2*ks+1][1] };
            uint32_t vrow = st + FSTG_K + ks * (16 * FROW);
            uint32_t vf[4][4], vs[2];
            #pragma unroll
            for (int t = 0; t < 4; t++)
                ldmx4t(vf[t], vrow + vfOff + t * 32);
            ldmx2t(vs, vrow + vsOff);
            #pragma unroll
            for (int dt = 0; dt < 8; dt++)
                mma_fp16(of[dt], pa, vf[dt >> 1][(dt & 1) * 2], vf[dt >> 1][(dt & 1) * 2 + 1]);
            mma_fp16(of[8], pa, vs[0], vs[1]);
        }
    }

    // epilogue: normalize by row sums, write ctx fp32
    const float inv0 = 1.f / of[8][0];
    const float inv1 = 1.f / of[8][2];
    const int r = qb + wid * 16 + (lid >> 2);
    const int c = h * DH + 2 * (lid & 3);
    float* o0 = g_ctx + (size_t)(b * TT + r) * DD + c;
    float* o1 = g_ctx + (size_t)(b * TT + r + 8) * DD + c;
    #pragma unroll
    for (int nt = 0; nt < 8; nt++) {
        float2 v0 = { of[nt][0] * inv0, of[nt][1] * inv0 };
        float2 v1 = { of[nt][2] * inv1, of[nt][3] * inv1 };
        *(float2*)(o0 + nt * 8) = v0;
        *(float2*)(o1 + nt * 8) = v1;
    }
}

// ---------------------------------------------------------------------------
extern "C" void kernel_launch(void* const* d_in, const int* in_sizes, int n_in,
                              void* d_out, int out_size)
{
    (void)in_sizes; (void)n_in; (void)out_size;
    const float* x  = (const float*)d_in[0];
    const float* Wq = (const float*)d_in[1];
    const float* bq = (const float*)d_in[2];
    const float* Wk = (const float*)d_in[3];
    const float* bk = (const float*)d_in[4];
    const float* Wv = (const float*)d_in[5];
    const float* bv = (const float*)d_in[6];
    const float* Wo = (const float*)d_in[7];
    const float* bo = (const float*)d_in[8];
    float* out = (float*)d_out;

    float* ctx;
    __half *qh, *kh, *vh;
    __nv_bfloat16 *abuf, *cbuf, *wbuf, *wobuf;
    cudaGetSymbolAddress((void**)&ctx,   g_ctx);
    cudaGetSymbolAddress((void**)&qh,    g_qh);
    cudaGetSymbolAddress((void**)&kh,    g_kh);
    cudaGetSymbolAddress((void**)&vh,    g_vh);
    cudaGetSymbolAddress((void**)&abuf,  g_abuf);
    cudaGetSymbolAddress((void**)&cbuf,  g_cbuf);
    cudaGetSymbolAddress((void**)&wbuf,  g_wbuf);
    cudaGetSymbolAddress((void**)&wobuf, g_wobuf);

    cudaFuncSetAttribute(mma_gemm,
                         cudaFuncAttributeMaxDynamicSharedMemorySize, GEMM_SMEM);

    // split inputs to bf16x3
    prep_triple<<<NTOK*DD/256, 256>>>(x,  abuf, NTOK*DD, 0);
    prep_triple<<<DD*DD/256,  256>>>(Wq, wbuf,                   DD*DD, 1);
    prep_triple<<<DD*DD/256,  256>>>(Wk, wbuf + (size_t)DD*KX,   DD*DD, 1);
    prep_triple<<<DD*DD/256,  256>>>(Wv, wbuf + (size_t)2*DD*KX, DD*DD, 1);
    prep_triple<<<DD*DD/256,  256>>>(Wo, wobuf,                  DD*DD, 1);

    // fused QKV projections -> fp16 (Q pre-scaled into log2 domain)
    mma_gemm<<<dim3(DD/128, NTOK/128, 3), 256, GEMM_SMEM>>>(
        abuf, wbuf, bq, bk, bv, nullptr, qh, kh, vh, 1);

    // tensorized causal flash attention
    flash_mma<<<dim3(TT/128, HH, BB), 256>>>();

    // output projection (fp32 out)
    prep_triple<<<NTOK*DD/256, 256>>>(ctx, cbuf, NTOK*DD, 0);
    mma_gemm<<<dim3(DD/128, NTOK/128, 1), 256, GEMM_SMEM>>>(
        cbuf, wobuf, bo, bo, bo, out, nullptr, nullptr, nullptr, 0);
}

// round 5
// speedup vs baseline: 4.4698x; 1.4596x over previous
#include <cuda_runtime.h>
#include <cuda_fp16.h>
#include <math.h>
#include <stdint.h>

#define BB 2
#define TT 2048
#define DD 1024
#define HH 16
#define DH 64
#define NTOK (BB*TT)
#define KX 2048                 // expanded K for fp16 weight-split (wh|wl)
#define NCH 64                  // 2048 / 32 K-chunks
#define NST 4                   // gemm pipeline stages
#define ROWB 80                 // gemm smem row stride bytes (64B data + 16 pad)
#define STAGE_B (128*ROWB*2)
#define A_HALF  (128*ROWB)
#define GEMM_SMEM (NST*STAGE_B)
#define QSCALE 0.1803368801f    // log2(e) / sqrt(64)

// flash smem geometry
#define FROW 144
#define FSTG_K 9216
#define FSTG   18432
#define FSMEM  36864

// Scratch (allocation forbidden; __device__ globals are the sanctioned path)
__device__ __half g_xh[NTOK*DD];                    // x in fp16
__device__ __half g_qh[NTOK*DD];                    // pre-scaled by QSCALE
__device__ __half g_kh[NTOK*DD];
__device__ __half g_vh[NTOK*DD];
__device__ __half g_ch[NTOK*DD];                    // ctx in fp16
__device__ __half g_wbuf[(size_t)3*DD*KX];          // [Wq|Wk|Wv] each [1024][2048]=(wh|wl)
__device__ __half g_wobuf[(size_t)DD*KX];           // Wo split

// ---------------------------------------------------------------------------
// PTX helpers
// ---------------------------------------------------------------------------
__device__ __forceinline__ uint32_t smem_u32(const void* p) {
    uint32_t a;
    asm("{ .reg .u64 t; cvta.to.shared.u64 t, %1; cvt.u32.u64 %0, t; }" : "=r"(a) : "l"(p));
    return a;
}
__device__ __forceinline__ void cpasync16(uint32_t saddr, const void* gaddr) {
    asm volatile("cp.async.cg.shared.global [%0], [%1], 16;" :: "r"(saddr), "l"(gaddr) : "memory");
}
__device__ __forceinline__ void cp_commit() { asm volatile("cp.async.commit_group;" ::: "memory"); }
__device__ __forceinline__ void cp_wait0()  { asm volatile("cp.async.wait_group 0;" ::: "memory"); }
__device__ __forceinline__ void cp_wait1()  { asm volatile("cp.async.wait_group 1;" ::: "memory"); }
__device__ __forceinline__ void cp_wait2()  { asm volatile("cp.async.wait_group 2;" ::: "memory"); }

__device__ __forceinline__ void ldmx4(uint32_t* r, uint32_t addr) {
    asm volatile("ldmatrix.sync.aligned.m8n8.x4.shared.b16 {%0,%1,%2,%3}, [%4];"
                 : "=r"(r[0]), "=r"(r[1]), "=r"(r[2]), "=r"(r[3]) : "r"(addr));
}
__device__ __forceinline__ void ldmx4t(uint32_t* r, uint32_t addr) {
    asm volatile("ldmatrix.sync.aligned.m8n8.x4.trans.shared.b16 {%0,%1,%2,%3}, [%4];"
                 : "=r"(r[0]), "=r"(r[1]), "=r"(r[2]), "=r"(r[3]) : "r"(addr));
}
__device__ __forceinline__ void ldmx2t(uint32_t* r, uint32_t addr) {
    asm volatile("ldmatrix.sync.aligned.m8n8.x2.trans.shared.b16 {%0,%1}, [%2];"
                 : "=r"(r[0]), "=r"(r[1]) : "r"(addr));
}
__device__ __forceinline__ void mma_fp16(float* c, const uint32_t* a, uint32_t b0, uint32_t b1) {
    asm volatile(
        "mma.sync.aligned.m16n8k16.row.col.f32.f16.f16.f32 "
        "{%0,%1,%2,%3}, {%4,%5,%6,%7}, {%8,%9}, {%0,%1,%2,%3};"
        : "+f"(c[0]), "+f"(c[1]), "+f"(c[2]), "+f"(c[3])
        : "r"(a[0]), "r"(a[1]), "r"(a[2]), "r"(a[3]), "r"(b0), "r"(b1));
}
__device__ __forceinline__ uint32_t packh2(float lo, float hi) {
    uint32_t u;
    asm("cvt.rn.f16x2.f32 %0, %1, %2;" : "=r"(u) : "f"(hi), "f"(lo));
    return u;
}
__device__ __forceinline__ float exp2_poly(float y) {
    float t = y + 12582912.f;
    float n = t - 12582912.f;
    float f = y - n;
    float p = fmaf(0.0555041f, f, 0.2440313f);
    p = fmaf(p, f, 0.6931472f);
    p = fmaf(p, f, 0.9999252f);
    return __int_as_float(__float_as_int(p) + (__float_as_int(t) << 23));
}
__device__ __forceinline__ float exp2_mufu(float y) {
    float r;
    asm("ex2.approx.f32 %0, %1;" : "=f"(r) : "f"(y));
    return r;
}

// ---------------------------------------------------------------------------
// Preps
// ---------------------------------------------------------------------------
__global__ void prep_half(const float* __restrict__ src, __half* __restrict__ dst, int n) {
    int i = (blockIdx.x * 256 + threadIdx.x) * 4;
    if (i >= n) return;
    float4 v = *(const float4*)(src + i);
    *(__half2*)(dst + i)     = __floats2half2_rn(v.x, v.y);
    *(__half2*)(dst + i + 2) = __floats2half2_rn(v.z, v.w);
}

// W[1024x1024] fp32 -> [wh | wl] fp16 at row stride 2048
__global__ void prep_wsplit(const float* __restrict__ w, __half* __restrict__ dst) {
    int i = blockIdx.x * 256 + threadIdx.x;
    int r = i >> 10, c = i & 1023;
    float v = w[i];
    __half hi = __float2half_rn(v);
    __half lo = __float2half_rn(v - __half2float(hi));
    size_t base = (size_t)r * KX + c;
    dst[base]        = hi;
    dst[base + 1024] = lo;
}

// ---------------------------------------------------------------------------
// HMMA GEMM (fp16 weight-split): C[4096,1024] = A[4096,1024] @ (Wh+Wl)^T + bias
// A chunks wrap mod 1024 (k in [1024,2048) re-reads A).
// half_out=1: fp16 out (z==0 scaled by QSCALE). half_out=0: fp32 out.
// ---------------------------------------------------------------------------
__device__ __forceinline__ void load_chunk(uint32_t stage_base,
    const __half* __restrict__ A, const __half* __restrict__ Wz,
    int mBase, int nBase, int chunk, int tid)
{
    const __half* Ab = A  + (size_t)mBase * DD + (chunk & 31) * 32;
    const __half* Bb = Wz + (size_t)nBase * KX + chunk * 32;
    #pragma unroll
    for (int j = 0; j < 2; j++) {
        int idx = tid + j * 256;
        int row = idx >> 2, g = idx & 3;
        cpasync16(stage_base + row * ROWB + g * 16,          Ab + (size_t)row * DD + g * 8);
        cpasync16(stage_base + A_HALF + row * ROWB + g * 16, Bb + (size_t)row * KX + g * 8);
    }
}

__global__ __launch_bounds__(256, 2) void mma_gemm(
    const __half* __restrict__ A, const __half* __restrict__ W,
    const float* b0p, const float* b1p, const float* b2p,
    float* o0, __half* h0, __half* h1, __half* h2, int half_out)
{
    extern __shared__ char sm_raw[];
    const uint32_t smem = smem_u32(sm_raw);

    const int tid = threadIdx.x;
    const int wid = tid >> 5, lid = tid & 31;
    const int warpM = wid >> 2;
    const int warpN = wid & 3;
    const int nBase = blockIdx.x * 128;
    const int mBase = blockIdx.y * 128;
    const int z = blockIdx.z;
    const __half* Wz = W + (size_t)z * DD * KX;
    const float* bias = (z == 0) ? b0p : (z == 1) ? b1p : b2p;

    float acc[4][4][4];
    #pragma unroll
    for (int mi = 0; mi < 4; mi++)
        #pragma unroll
        for (int nj = 0; nj < 4; nj++)
            #pragma unroll
            for (int e = 0; e < 4; e++) acc[mi][nj][e] = 0.f;

    const uint32_t aOff = (uint32_t)(warpM * 64 + (lid & 15)) * ROWB + ((lid >> 4) << 4);
    const uint32_t bOff = A_HALF +
        (uint32_t)(warpN * 32 + (lid & 7) + ((lid >> 4) << 3)) * ROWB + (((lid >> 3) & 1) << 4);

    #pragma unroll
    for (int s = 0; s < NST - 1; s++) {
        load_chunk(smem + s * STAGE_B, A, Wz, mBase, nBase, s, tid);
        cp_commit();
    }

    for (int i = 0; i < NCH; i++) {
        const uint32_t st = smem + (i & (NST - 1)) * STAGE_B;
        cp_wait2();
        __syncthreads();

        int nxt = i + NST - 1;
        if (nxt < NCH) {
            load_chunk(smem + (nxt & (NST - 1)) * STAGE_B, A, Wz, mBase, nBase, nxt, tid);
            cp_commit();
        }

        #pragma unroll
        for (int kp = 0; kp < 2; kp++) {
            const uint32_t kOff = kp * 32;
            uint32_t af[4][4], bf[2][4];
            #pragma unroll
            for (int mi = 0; mi < 4; mi++)
                ldmx4(af[mi], st + aOff + mi * (16 * ROWB) + kOff);
            #pragma unroll
            for (int g = 0; g < 2; g++)
                ldmx4(bf[g], st + bOff + g * (16 * ROWB) + kOff);
            #pragma unroll
            for (int mi = 0; mi < 4; mi++)
                #pragma unroll
                for (int nj = 0; nj < 4; nj++)
                    mma_fp16(acc[mi][nj], af[mi], bf[nj >> 1][(nj & 1) * 2], bf[nj >> 1][(nj & 1) * 2 + 1]);
        }
    }

    const int rBase = mBase + warpM * 64 + (lid >> 2);
    const int cBase = nBase + warpN * 32 + (lid & 3) * 2;
    if (half_out) {
        __half* hp = (z == 0) ? h0 : (z == 1) ? h1 : h2;
        const float sc = (z == 0) ? QSCALE : 1.f;
        #pragma unroll
        for (int mi = 0; mi < 4; mi++) {
            #pragma unroll
            for (int nj = 0; nj < 4; nj++) {
                int col = cBase + nj * 8;
                float bx = bias[col], by = bias[col + 1];
                int r0 = rBase + mi * 16;
                __half2 v0 = __floats2half2_rn((acc[mi][nj][0] + bx) * sc, (acc[mi][nj][1] + by) * sc);
                __half2 v1 = __floats2half2_rn((acc[mi][nj][2] + bx) * sc, (acc[mi][nj][3] + by) * sc);
                *(__half2*)(hp + (size_t)r0 * DD + col)       = v0;
                *(__half2*)(hp + (size_t)(r0 + 8) * DD + col) = v1;
            }
        }
    } else {
        #pragma unroll
        for (int mi = 0; mi < 4; mi++) {
            #pragma unroll
            for (int nj = 0; nj < 4; nj++) {
                int col = cBase + nj * 8;
                float bx = bias[col], by = bias[col + 1];
                int r0 = rBase + mi * 16;
                float2 v0 = { acc[mi][nj][0] + bx, acc[mi][nj][1] + by };
                float2 v1 = { acc[mi][nj][2] + bx, acc[mi][nj][3] + by };
                *(float2*)(o0 + (size_t)r0 * DD + col)       = v0;
                *(float2*)(o0 + (size_t)(r0 + 8) * DD + col) = v1;
            }
        }
    }
}

// ---------------------------------------------------------------------------
// Tensorized causal flash attention (fp16 mma, no-max softmax, log2 domain).
// Writes ctx directly in fp16.
// ---------------------------------------------------------------------------
__global__ __launch_bounds__(256) void flash_mma()
{
    __shared__ __align__(1024) char sm_f[FSMEM];
    const uint32_t base = smem_u32(sm_f);

    const int tid = threadIdx.x;
    const int wid = tid >> 5, lid = tid & 31;
    const int qt = 15 - blockIdx.x;
    const int h  = blockIdx.y;
    const int b  = blockIdx.z;
    const int qb = qt * 128;
    const int nk = (qt + 1) * 2;

    const __half* qp  = g_qh + (size_t)(b * TT + qb) * DD + h * DH;
    const __half* kp0 = g_kh + (size_t)(b * TT) * DD + h * DH;
    const __half* vp0 = g_vh + (size_t)(b * TT) * DD + h * DH;

    // stage Q through smem, grab A-frags
    #pragma unroll
    for (int j = 0; j < 4; j++) {
        int idx = tid + j * 256;
        int row = idx >> 3, g = idx & 7;
        cpasync16(base + row * FROW + g * 16, qp + (size_t)row * DD + g * 8);
    }
    cp_commit(); cp_wait0();
    __syncthreads();
    uint32_t qf[4][4];
    const uint32_t qaddr = base + (uint32_t)(wid * 16 + (lid & 15)) * FROW + ((lid >> 4) << 4);
    #pragma unroll
    for (int ks = 0; ks < 4; ks++) ldmx4(qf[ks], qaddr + ks * 32);
    __syncthreads();

    // ones columns for both V stages
    if (tid < 128) {
        int s = tid >> 6, r = tid & 63;
        uint4 ones = { 0x3C003C00u, 0x3C003C00u, 0x3C003C00u, 0x3C003C00u };
        *(uint4*)(sm_f + s * FSTG + FSTG_K + r * FROW + 128) = ones;
    }

    // preload ktile 0
    {
        #pragma unroll
        for (int j = 0; j < 2; j++) {
            int idx = tid + j * 256;
            int row = idx >> 3, g = idx & 7;
            cpasync16(base + row * FROW + g * 16,          kp0 + (size_t)row * DD + g * 8);
            cpasync16(base + FSTG_K + row * FROW + g * 16, vp0 + (size_t)row * DD + g * 8);
        }
        cp_commit();
    }

    float of[9][4];
    #pragma unroll
    for (int t = 0; t < 9; t++)
        #pragma unroll
        for (int e = 0; e < 4; e++) of[t][e] = 0.f;

    const uint32_t kfOff = (uint32_t)((lid & 7) + ((lid >> 4) << 3)) * FROW + (((lid >> 3) & 1) << 4);
    const uint32_t vfOff = (uint32_t)((lid & 7) + (((lid >> 3) & 1) << 3)) * FROW + ((lid >> 4) << 4);
    const uint32_t vsOff = (uint32_t)((lid & 7) + (((lid >> 3) & 1) << 3)) * FROW + 128;

    for (int kt = 0; kt < nk; kt++) {
        const int s = kt & 1;
        const int kb = kt * 64;
        __syncthreads();
        if (kt + 1 < nk) {
            const __half* kp = kp0 + (size_t)(kb + 64) * DD;
            const __half* vp = vp0 + (size_t)(kb + 64) * DD;
            uint32_t sb = base + (s ^ 1) * FSTG;
            #pragma unroll
            for (int j = 0; j < 2; j++) {
                int idx = tid + j * 256;
                int row = idx >> 3, g = idx & 7;
                cpasync16(sb + row * FROW + g * 16,          kp + (size_t)row * DD + g * 8);
                cpasync16(sb + FSTG_K + row * FROW + g * 16, vp + (size_t)row * DD + g * 8);
            }
            cp_commit(); cp_wait1();
        } else {
            cp_wait0();
        }
        __syncthreads();

        const uint32_t st = base + s * FSTG;

        float sf[8][4];
        #pragma unroll
        for (int t = 0; t < 8; t++)
            #pragma unroll
            for (int e = 0; e < 4; e++) sf[t][e] = 0.f;

        #pragma unroll
        for (int ks = 0; ks < 4; ks++) {
            uint32_t bf[4][4];
            #pragma unroll
            for (int t = 0; t < 4; t++)
                ldmx4(bf[t], st + kfOff + t * (16 * FROW) + ks * 32);
            #pragma unroll
            for (int nt = 0; nt < 8; nt++)
                mma_fp16(sf[nt], qf[ks], bf[nt >> 1][(nt & 1) * 2], bf[nt >> 1][(nt & 1) * 2 + 1]);
        }

        if (kb + 63 > qb) {
            const int r0 = qb + wid * 16 + (lid >> 2);
            const int c0 = kb + 2 * (lid & 3);
            #pragma unroll
            for (int nt = 0; nt < 8; nt++)
                #pragma unroll
                for (int e = 0; e < 4; e++) {
                    int col = c0 + nt * 8 + (e & 1);
                    int row = r0 + (e >> 1) * 8;
                    if (col > row) sf[nt][e] = -60.f;
                }
        }

        uint32_t pf[8][2];
        #pragma unroll
        for (int nt = 0; nt < 8; nt++) {
            float p0, p1, p2, p3;
            if ((nt & 3) == 3) {
                p0 = exp2_mufu(sf[nt][0]); p1 = exp2_mufu(sf[nt][1]);
                p2 = exp2_mufu(sf[nt][2]); p3 = exp2_mufu(sf[nt][3]);
            } else {
                p0 = exp2_poly(sf[nt][0]); p1 = exp2_poly(sf[nt][1]);
                p2 = exp2_poly(sf[nt][2]); p3 = exp2_poly(sf[nt][3]);
            }
            pf[nt][0] = packh2(p0, p1);
            pf[nt][1] = packh2(p2, p3);
        }

        #pragma unroll
        for (int ks = 0; ks < 4; ks++) {
            uint32_t pa[4] = { pf[2*ks][0], pf[2*ks][1], pf[2*ks+1][0], pf[2*ks+1][1] };
            uint32_t vrow = st + FSTG_K + ks * (16 * FROW);
            uint32_t vf[4][4], vs[2];
            #pragma unroll
            for (int t = 0; t < 4; t++)
                ldmx4t(vf[t], vrow + vfOff + t * 32);
            ldmx2t(vs, vrow + vsOff);
            #pragma unroll
            for (int dt = 0; dt < 8; dt++)
                mma_fp16(of[dt], pa, vf[dt >> 1][(dt & 1) * 2], vf[dt >> 1][(dt & 1) * 2 + 1]);
            mma_fp16(of[8], pa, vs[0], vs[1]);
        }
    }

    // epilogue: normalize, write ctx fp16
    const float inv0 = 1.f / of[8][0];
    const float inv1 = 1.f / of[8][2];
    const int r = qb + wid * 16 + (lid >> 2);
    const int c = h * DH + 2 * (lid & 3);
    __half* o0 = g_ch + (size_t)(b * TT + r) * DD + c;
    __half* o1 = g_ch + (size_t)(b * TT + r + 8) * DD + c;
    #pragma unroll
    for (int nt = 0; nt < 8; nt++) {
        *(__half2*)(o0 + nt * 8) = __floats2half2_rn(of[nt][0] * inv0, of[nt][1] * inv0);
        *(__half2*)(o1 + nt * 8) = __floats2half2_rn(of[nt][2] * inv1, of[nt][3] * inv1);
    }
}

// ---------------------------------------------------------------------------
extern "C" void kernel_launch(void* const* d_in, const int* in_sizes, int n_in,
                              void* d_out, int out_size)
{
    (void)in_sizes; (void)n_in; (void)out_size;
    const float* x  = (const float*)d_in[0];
    const float* Wq = (const float*)d_in[1];
    const float* bq = (const float*)d_in[2];
    const float* Wk = (const float*)d_in[3];
    const float* bk = (const float*)d_in[4];
    const float* Wv = (const float*)d_in[5];
    const float* bv = (const float*)d_in[6];
    const float* Wo = (const float*)d_in[7];
    const float* bo = (const float*)d_in[8];
    float* out = (float*)d_out;

    __half *xh, *qh, *kh, *vh, *ch, *wbuf, *wobuf;
    cudaGetSymbolAddress((void**)&xh,    g_xh);
    cudaGetSymbolAddress((void**)&qh,    g_qh);
    cudaGetSymbolAddress((void**)&kh,    g_kh);
    cudaGetSymbolAddress((void**)&vh,    g_vh);
    cudaGetSymbolAddress((void**)&ch,    g_ch);
    cudaGetSymbolAddress((void**)&wbuf,  g_wbuf);
    cudaGetSymbolAddress((void**)&wobuf, g_wobuf);

    cudaFuncSetAttribute(mma_gemm,
                         cudaFuncAttributeMaxDynamicSharedMemorySize, GEMM_SMEM);

    // preps
    prep_half<<<NTOK*DD/1024, 256>>>(x, xh, NTOK*DD);
    prep_wsplit<<<DD*DD/256, 256>>>(Wq, wbuf);
    prep_wsplit<<<DD*DD/256, 256>>>(Wk, wbuf + (size_t)DD*KX);
    prep_wsplit<<<DD*DD/256, 256>>>(Wv, wbuf + (size_t)2*DD*KX);
    prep_wsplit<<<DD*DD/256, 256>>>(Wo, wobuf);

    // fused QKV projections -> fp16 (Q pre-scaled into log2 domain)
    mma_gemm<<<dim3(DD/128, NTOK/128, 3), 256, GEMM_SMEM>>>(
        xh, wbuf, bq, bk, bv, nullptr, qh, kh, vh, 1);

    // tensorized causal flash attention (writes ctx fp16)
    flash_mma<<<dim3(TT/128, HH, BB), 256>>>();

    // output projection (fp32 out + bias)
    mma_gemm<<<dim3(DD/128, NTOK/128, 1), 256, GEMM_SMEM>>>(
        ch, wobuf, bo, bo, bo, out, nullptr, nullptr, nullptr, 0);
}

// round 6
// speedup vs baseline: 6.5130x; 1.4571x over previous
#include <cuda_runtime.h>
#include <cuda_fp16.h>
#include <math.h>
#include <stdint.h>

#define BB 2
#define TT 2048
#define DD 1024
#define HH 16
#define DH 64
#define NTOK (BB*TT)
#define NCH 32                  // 1024 / 32 K-chunks (single-term fp16)
#define NST 4                   // gemm pipeline stages
#define ROWB 80                 // gemm smem row stride bytes (64B data + 16 pad)
#define STAGE_B (128*ROWB*2)
#define A_HALF  (128*ROWB)
#define GEMM_SMEM (NST*STAGE_B)
#define QSCALE 0.1803368801f    // log2(e) / sqrt(64)

// flash smem geometry
#define FROW 144
#define FSTG_K 9216
#define FSTG   18432
#define FSMEM  36864

// Scratch (allocation forbidden; __device__ globals are the sanctioned path)
__device__ __half g_xh[NTOK*DD];                    // x in fp16
__device__ __half g_qh[NTOK*DD];                    // pre-scaled by QSCALE
__device__ __half g_kh[NTOK*DD];
__device__ __half g_vh[NTOK*DD];
__device__ __half g_ch[NTOK*DD];                    // ctx in fp16
__device__ __half g_wbuf[(size_t)3*DD*DD];          // Wq|Wk|Wv fp16
__device__ __half g_wobuf[(size_t)DD*DD];           // Wo fp16

// ---------------------------------------------------------------------------
// PTX helpers
// ---------------------------------------------------------------------------
__device__ __forceinline__ uint32_t smem_u32(const void* p) {
    uint32_t a;
    asm("{ .reg .u64 t; cvta.to.shared.u64 t, %1; cvt.u32.u64 %0, t; }" : "=r"(a) : "l"(p));
    return a;
}
__device__ __forceinline__ void cpasync16(uint32_t saddr, const void* gaddr) {
    asm volatile("cp.async.cg.shared.global [%0], [%1], 16;" :: "r"(saddr), "l"(gaddr) : "memory");
}
__device__ __forceinline__ void cp_commit() { asm volatile("cp.async.commit_group;" ::: "memory"); }
__device__ __forceinline__ void cp_wait0()  { asm volatile("cp.async.wait_group 0;" ::: "memory"); }
__device__ __forceinline__ void cp_wait1()  { asm volatile("cp.async.wait_group 1;" ::: "memory"); }
__device__ __forceinline__ void cp_wait2()  { asm volatile("cp.async.wait_group 2;" ::: "memory"); }

__device__ __forceinline__ void ldmx4(uint32_t* r, uint32_t addr) {
    asm volatile("ldmatrix.sync.aligned.m8n8.x4.shared.b16 {%0,%1,%2,%3}, [%4];"
                 : "=r"(r[0]), "=r"(r[1]), "=r"(r[2]), "=r"(r[3]) : "r"(addr));
}
__device__ __forceinline__ void ldmx4t(uint32_t* r, uint32_t addr) {
    asm volatile("ldmatrix.sync.aligned.m8n8.x4.trans.shared.b16 {%0,%1,%2,%3}, [%4];"
                 : "=r"(r[0]), "=r"(r[1]), "=r"(r[2]), "=r"(r[3]) : "r"(addr));
}
__device__ __forceinline__ void ldmx2t(uint32_t* r, uint32_t addr) {
    asm volatile("ldmatrix.sync.aligned.m8n8.x2.trans.shared.b16 {%0,%1}, [%2];"
                 : "=r"(r[0]), "=r"(r[1]) : "r"(addr));
}
__device__ __forceinline__ void mma_fp16(float* c, const uint32_t* a, uint32_t b0, uint32_t b1) {
    asm volatile(
        "mma.sync.aligned.m16n8k16.row.col.f32.f16.f16.f32 "
        "{%0,%1,%2,%3}, {%4,%5,%6,%7}, {%8,%9}, {%0,%1,%2,%3};"
        : "+f"(c[0]), "+f"(c[1]), "+f"(c[2]), "+f"(c[3])
        : "r"(a[0]), "r"(a[1]), "r"(a[2]), "r"(a[3]), "r"(b0), "r"(b1));
}
__device__ __forceinline__ uint32_t packh2(float lo, float hi) {
    uint32_t u;
    asm("cvt.rn.f16x2.f32 %0, %1, %2;" : "=r"(u) : "f"(hi), "f"(lo));
    return u;
}
__device__ __forceinline__ float exp2_poly(float y) {
    float t = y + 12582912.f;
    float n = t - 12582912.f;
    float f = y - n;
    float p = fmaf(0.0555041f, f, 0.2440313f);
    p = fmaf(p, f, 0.6931472f);
    p = fmaf(p, f, 0.9999252f);
    return __int_as_float(__float_as_int(p) + (__float_as_int(t) << 23));
}
__device__ __forceinline__ float exp2_mufu(float y) {
    float r;
    asm("ex2.approx.f32 %0, %1;" : "=f"(r) : "f"(y));
    return r;
}

// ---------------------------------------------------------------------------
// Prep: fp32 -> fp16 convert (used for x and all weights)
// ---------------------------------------------------------------------------
__global__ void prep_half(const float* __restrict__ src, __half* __restrict__ dst, int n) {
    int i = (blockIdx.x * 256 + threadIdx.x) * 4;
    if (i >= n) return;
    float4 v = *(const float4*)(src + i);
    *(__half2*)(dst + i)     = __floats2half2_rn(v.x, v.y);
    *(__half2*)(dst + i + 2) = __floats2half2_rn(v.z, v.w);
}

// ---------------------------------------------------------------------------
// HMMA GEMM (single fp16): C[4096,1024] = A[4096,1024] @ W[1024,1024]^T + bias
// half_out=1: fp16 out (z==0 scaled by QSCALE). half_out=0: fp32 out.
// ---------------------------------------------------------------------------
__device__ __forceinline__ void load_chunk(uint32_t stage_base,
    const __half* __restrict__ A, const __half* __restrict__ Wz,
    int mBase, int nBase, int chunk, int tid)
{
    const __half* Ab = A  + (size_t)mBase * DD + chunk * 32;
    const __half* Bb = Wz + (size_t)nBase * DD + chunk * 32;
    #pragma unroll
    for (int j = 0; j < 2; j++) {
        int idx = tid + j * 256;
        int row = idx >> 2, g = idx & 3;
        cpasync16(stage_base + row * ROWB + g * 16,          Ab + (size_t)row * DD + g * 8);
        cpasync16(stage_base + A_HALF + row * ROWB + g * 16, Bb + (size_t)row * DD + g * 8);
    }
}

__global__ __launch_bounds__(256, 2) void mma_gemm(
    const __half* __restrict__ A, const __half* __restrict__ W,
    const float* b0p, const float* b1p, const float* b2p,
    float* o0, __half* h0, __half* h1, __half* h2, int half_out)
{
    extern __shared__ char sm_raw[];
    const uint32_t smem = smem_u32(sm_raw);

    const int tid = threadIdx.x;
    const int wid = tid >> 5, lid = tid & 31;
    const int warpM = wid >> 2;
    const int warpN = wid & 3;
    const int nBase = blockIdx.x * 128;
    const int mBase = blockIdx.y * 128;
    const int z = blockIdx.z;
    const __half* Wz = W + (size_t)z * DD * DD;
    const float* bias = (z == 0) ? b0p : (z == 1) ? b1p : b2p;

    float acc[4][4][4];
    #pragma unroll
    for (int mi = 0; mi < 4; mi++)
        #pragma unroll
        for (int nj = 0; nj < 4; nj++)
            #pragma unroll
            for (int e = 0; e < 4; e++) acc[mi][nj][e] = 0.f;

    const uint32_t aOff = (uint32_t)(warpM * 64 + (lid & 15)) * ROWB + ((lid >> 4) << 4);
    const uint32_t bOff = A_HALF +
        (uint32_t)(warpN * 32 + (lid & 7) + ((lid >> 4) << 3)) * ROWB + (((lid >> 3) & 1) << 4);

    #pragma unroll
    for (int s = 0; s < NST - 1; s++) {
        load_chunk(smem + s * STAGE_B, A, Wz, mBase, nBase, s, tid);
        cp_commit();
    }

    for (int i = 0; i < NCH; i++) {
        const uint32_t st = smem + (i & (NST - 1)) * STAGE_B;
        cp_wait2();
        __syncthreads();

        int nxt = i + NST - 1;
        if (nxt < NCH) {
            load_chunk(smem + (nxt & (NST - 1)) * STAGE_B, A, Wz, mBase, nBase, nxt, tid);
            cp_commit();
        }

        #pragma unroll
        for (int kp = 0; kp < 2; kp++) {
            const uint32_t kOff = kp * 32;
            uint32_t af[4][4], bf[2][4];
            #pragma unroll
            for (int mi = 0; mi < 4; mi++)
                ldmx4(af[mi], st + aOff + mi * (16 * ROWB) + kOff);
            #pragma unroll
            for (int g = 0; g < 2; g++)
                ldmx4(bf[g], st + bOff + g * (16 * ROWB) + kOff);
            #pragma unroll
            for (int mi = 0; mi < 4; mi++)
                #pragma unroll
                for (int nj = 0; nj < 4; nj++)
                    mma_fp16(acc[mi][nj], af[mi], bf[nj >> 1][(nj & 1) * 2], bf[nj >> 1][(nj & 1) * 2 + 1]);
        }
    }

    const int rBase = mBase + warpM * 64 + (lid >> 2);
    const int cBase = nBase + warpN * 32 + (lid & 3) * 2;
    if (half_out) {
        __half* hp = (z == 0) ? h0 : (z == 1) ? h1 : h2;
        const float sc = (z == 0) ? QSCALE : 1.f;
        #pragma unroll
        for (int mi = 0; mi < 4; mi++) {
            #pragma unroll
            for (int nj = 0; nj < 4; nj++) {
                int col = cBase + nj * 8;
                float bx = bias[col], by = bias[col + 1];
                int r0 = rBase + mi * 16;
                __half2 v0 = __floats2half2_rn((acc[mi][nj][0] + bx) * sc, (acc[mi][nj][1] + by) * sc);
                __half2 v1 = __floats2half2_rn((acc[mi][nj][2] + bx) * sc, (acc[mi][nj][3] + by) * sc);
                *(__half2*)(hp + (size_t)r0 * DD + col)       = v0;
                *(__half2*)(hp + (size_t)(r0 + 8) * DD + col) = v1;
            }
        }
    } else {
        #pragma unroll
        for (int mi = 0; mi < 4; mi++) {
            #pragma unroll
            for (int nj = 0; nj < 4; nj++) {
                int col = cBase + nj * 8;
                float bx = bias[col], by = bias[col + 1];
                int r0 = rBase + mi * 16;
                float2 v0 = { acc[mi][nj][0] + bx, acc[mi][nj][1] + by };
                float2 v1 = { acc[mi][nj][2] + bx, acc[mi][nj][3] + by };
                *(float2*)(o0 + (size_t)r0 * DD + col)       = v0;
                *(float2*)(o0 + (size_t)(r0 + 8) * DD + col) = v1;
            }
        }
    }
}

// ---------------------------------------------------------------------------
// Tensorized causal flash attention (fp16 mma, no-max softmax, log2 domain).
// Writes ctx directly in fp16.
// ---------------------------------------------------------------------------
__global__ __launch_bounds__(256) void flash_mma()
{
    __shared__ __align__(1024) char sm_f[FSMEM];
    const uint32_t base = smem_u32(sm_f);

    const int tid = threadIdx.x;
    const int wid = tid >> 5, lid = tid & 31;
    const int qt = 15 - blockIdx.x;
    const int h  = blockIdx.y;
    const int b  = blockIdx.z;
    const int qb = qt * 128;
    const int nk = (qt + 1) * 2;

    const __half* qp  = g_qh + (size_t)(b * TT + qb) * DD + h * DH;
    const __half* kp0 = g_kh + (size_t)(b * TT) * DD + h * DH;
    const __half* vp0 = g_vh + (size_t)(b * TT) * DD + h * DH;

    // stage Q through smem, grab A-frags
    #pragma unroll
    for (int j = 0; j < 4; j++) {
        int idx = tid + j * 256;
        int row = idx >> 3, g = idx & 7;
        cpasync16(base + row * FROW + g * 16, qp + (size_t)row * DD + g * 8);
    }
    cp_commit(); cp_wait0();
    __syncthreads();
    uint32_t qf[4][4];
    const uint32_t qaddr = base + (uint32_t)(wid * 16 + (lid & 15)) * FROW + ((lid >> 4) << 4);
    #pragma unroll
    for (int ks = 0; ks < 4; ks++) ldmx4(qf[ks], qaddr + ks * 32);
    __syncthreads();

    // ones columns for both V stages
    if (tid < 128) {
        int s = tid >> 6, r = tid & 63;
        uint4 ones = { 0x3C003C00u, 0x3C003C00u, 0x3C003C00u, 0x3C003C00u };
        *(uint4*)(sm_f + s * FSTG + FSTG_K + r * FROW + 128) = ones;
    }

    // preload ktile 0
    {
        #pragma unroll
        for (int j = 0; j < 2; j++) {
            int idx = tid + j * 256;
            int row = idx >> 3, g = idx & 7;
            cpasync16(base + row * FROW + g * 16,          kp0 + (size_t)row * DD + g * 8);
            cpasync16(base + FSTG_K + row * FROW + g * 16, vp0 + (size_t)row * DD + g * 8);
        }
        cp_commit();
    }

    float of[9][4];
    #pragma unroll
    for (int t = 0; t < 9; t++)
        #pragma unroll
        for (int e = 0; e < 4; e++) of[t][e] = 0.f;

    const uint32_t kfOff = (uint32_t)((lid & 7) + ((lid >> 4) << 3)) * FROW + (((lid >> 3) & 1) << 4);
    const uint32_t vfOff = (uint32_t)((lid & 7) + (((lid >> 3) & 1) << 3)) * FROW + ((lid >> 4) << 4);
    const uint32_t vsOff = (uint32_t)((lid & 7) + (((lid >> 3) & 1) << 3)) * FROW + 128;

    for (int kt = 0; kt < nk; kt++) {
        const int s = kt & 1;
        const int kb = kt * 64;
        __syncthreads();
        if (kt + 1 < nk) {
            const __half* kp = kp0 + (size_t)(kb + 64) * DD;
            const __half* vp = vp0 + (size_t)(kb + 64) * DD;
            uint32_t sb = base + (s ^ 1) * FSTG;
            #pragma unroll
            for (int j = 0; j < 2; j++) {
                int idx = tid + j * 256;
                int row = idx >> 3, g = idx & 7;
                cpasync16(sb + row * FROW + g * 16,          kp + (size_t)row * DD + g * 8);
                cpasync16(sb + FSTG_K + row * FROW + g * 16, vp + (size_t)row * DD + g * 8);
            }
            cp_commit(); cp_wait1();
        } else {
            cp_wait0();
        }
        __syncthreads();

        const uint32_t st = base + s * FSTG;

        float sf[8][4];
        #pragma unroll
        for (int t = 0; t < 8; t++)
            #pragma unroll
            for (int e = 0; e < 4; e++) sf[t][e] = 0.f;

        #pragma unroll
        for (int ks = 0; ks < 4; ks++) {
            uint32_t bf[4][4];
            #pragma unroll
            for (int t = 0; t < 4; t++)
                ldmx4(bf[t], st + kfOff + t * (16 * FROW) + ks * 32);
            #pragma unroll
            for (int nt = 0; nt < 8; nt++)
                mma_fp16(sf[nt], qf[ks], bf[nt >> 1][(nt & 1) * 2], bf[nt >> 1][(nt & 1) * 2 + 1]);
        }

        if (kb + 63 > qb) {
            const int r0 = qb + wid * 16 + (lid >> 2);
            const int c0 = kb + 2 * (lid & 3);
            #pragma unroll
            for (int nt = 0; nt < 8; nt++)
                #pragma unroll
                for (int e = 0; e < 4; e++) {
                    int col = c0 + nt * 8 + (e & 1);
                    int row = r0 + (e >> 1) * 8;
                    if (col > row) sf[nt][e] = -60.f;
                }
        }

        uint32_t pf[8][2];
        #pragma unroll
        for (int nt = 0; nt < 8; nt++) {
            float p0, p1, p2, p3;
            if ((nt & 3) == 3) {
                p0 = exp2_mufu(sf[nt][0]); p1 = exp2_mufu(sf[nt][1]);
                p2 = exp2_mufu(sf[nt][2]); p3 = exp2_mufu(sf[nt][3]);
            } else {
                p0 = exp2_poly(sf[nt][0]); p1 = exp2_poly(sf[nt][1]);
                p2 = exp2_poly(sf[nt][2]); p3 = exp2_poly(sf[nt][3]);
            }
            pf[nt][0] = packh2(p0, p1);
            pf[nt][1] = packh2(p2, p3);
        }

        #pragma unroll
        for (int ks = 0; ks < 4; ks++) {
            uint32_t pa[4] = { pf[2*ks][0], pf[2*ks][1], pf[2*ks+1][0], pf[2*ks+1][1] };
            uint32_t vrow = st + FSTG_K + ks * (16 * FROW);
            uint32_t vf[4][4], vs[2];
            #pragma unroll
            for (int t = 0; t < 4; t++)
                ldmx4t(vf[t], vrow + vfOff + t * 32);
            ldmx2t(vs, vrow + vsOff);
            #pragma unroll
            for (int dt = 0; dt < 8; dt++)
                mma_fp16(of[dt], pa, vf[dt >> 1][(dt & 1) * 2], vf[dt >> 1][(dt & 1) * 2 + 1]);
            mma_fp16(of[8], pa, vs[0], vs[1]);
        }
    }

    // epilogue: normalize, write ctx fp16
    const float inv0 = 1.f / of[8][0];
    const float inv1 = 1.f / of[8][2];
    const int r = qb + wid * 16 + (lid >> 2);
    const int c = h * DH + 2 * (lid & 3);
    __half* o0 = g_ch + (size_t)(b * TT + r) * DD + c;
    __half* o1 = g_ch + (size_t)(b * TT + r + 8) * DD + c;
    #pragma unroll
    for (int nt = 0; nt < 8; nt++) {
        *(__half2*)(o0 + nt * 8) = __floats2half2_rn(of[nt][0] * inv0, of[nt][1] * inv0);
        *(__half2*)(o1 + nt * 8) = __floats2half2_rn(of[nt][2] * inv1, of[nt][3] * inv1);
    }
}

// ---------------------------------------------------------------------------
extern "C" void kernel_launch(void* const* d_in, const int* in_sizes, int n_in,
                              void* d_out, int out_size)
{
    (void)in_sizes; (void)n_in; (void)out_size;
    const float* x  = (const float*)d_in[0];
    const float* Wq = (const float*)d_in[1];
    const float* bq = (const float*)d_in[2];
    const float* Wk = (const float*)d_in[3];
    const float* bk = (const float*)d_in[4];
    const float* Wv = (const float*)d_in[5];
    const float* bv = (const float*)d_in[6];
    const float* Wo = (const float*)d_in[7];
    const float* bo = (const float*)d_in[8];
    float* out = (float*)d_out;

    __half *xh, *qh, *kh, *vh, *ch, *wbuf, *wobuf;
    cudaGetSymbolAddress((void**)&xh,    g_xh);
    cudaGetSymbolAddress((void**)&qh,    g_qh);
    cudaGetSymbolAddress((void**)&kh,    g_kh);
    cudaGetSymbolAddress((void**)&vh,    g_vh);
    cudaGetSymbolAddress((void**)&ch,    g_ch);
    cudaGetSymbolAddress((void**)&wbuf,  g_wbuf);
    cudaGetSymbolAddress((void**)&wobuf, g_wobuf);

    cudaFuncSetAttribute(mma_gemm,
                         cudaFuncAttributeMaxDynamicSharedMemorySize, GEMM_SMEM);

    // preps: plain fp32 -> fp16 converts
    prep_half<<<NTOK*DD/1024, 256>>>(x, xh, NTOK*DD);
    prep_half<<<DD*DD/1024, 256>>>(Wq, wbuf,                 DD*DD);
    prep_half<<<DD*DD/1024, 256>>>(Wk, wbuf + (size_t)DD*DD,   DD*DD);
    prep_half<<<DD*DD/1024, 256>>>(Wv, wbuf + (size_t)2*DD*DD, DD*DD);
    prep_half<<<DD*DD/1024, 256>>>(Wo, wobuf,                DD*DD);

    // fused QKV projections -> fp16 (Q pre-scaled into log2 domain)
    mma_gemm<<<dim3(DD/128, NTOK/128, 3), 256, GEMM_SMEM>>>(
        xh, wbuf, bq, bk, bv, nullptr, qh, kh, vh, 1);

    // tensorized causal flash attention (writes ctx fp16)
    flash_mma<<<dim3(TT/128, HH, BB), 256>>>();

    // output projection (fp32 out + bias)
    mma_gemm<<<dim3(DD/128, NTOK/128, 1), 256, GEMM_SMEM>>>(
        ch, wobuf, bo, bo, bo, out, nullptr, nullptr, nullptr, 0);
}

// round 7
// speedup vs baseline: 6.8842x; 1.0570x over previous
#include <cuda_runtime.h>
#include <cuda_fp16.h>
#include <math.h>
#include <stdint.h>

#define BB 2
#define TT 2048
#define DD 1024
#define HH 16
#define DH 64
#define NTOK (BB*TT)
#define NCH 32                  // 1024 / 32 K-chunks (single-term fp16)
#define NST 4                   // gemm pipeline stages
#define ROWB 80                 // gemm smem row stride bytes (64B data + 16 pad)
#define STAGE_B (128*ROWB*2)
#define A_HALF  (128*ROWB)
#define GEMM_SMEM (NST*STAGE_B)
#define QSCALE 0.1803368801f    // log2(e) / sqrt(64)

// flash smem geometry
#define FROW 144
#define FSTG_K 9216
#define FSTG   18432
#define FSMEM  36864

// Scratch (allocation forbidden; __device__ globals are the sanctioned path)
__device__ __half g_xh[NTOK*DD];                    // x in fp16
__device__ __half g_qh[NTOK*DD];                    // pre-scaled by QSCALE
__device__ __half g_kh[NTOK*DD];
__device__ __half g_vh[NTOK*DD];
__device__ __half g_ch[NTOK*DD];                    // ctx in fp16
__device__ __half g_wbuf[(size_t)3*DD*DD];          // Wq|Wk|Wv fp16
__device__ __half g_wobuf[(size_t)DD*DD];           // Wo fp16

// ---------------------------------------------------------------------------
// PTX helpers
// ---------------------------------------------------------------------------
__device__ __forceinline__ uint32_t smem_u32(const void* p) {
    uint32_t a;
    asm("{ .reg .u64 t; cvta.to.shared.u64 t, %1; cvt.u32.u64 %0, t; }" : "=r"(a) : "l"(p));
    return a;
}
__device__ __forceinline__ void cpasync16(uint32_t saddr, const void* gaddr) {
    asm volatile("cp.async.cg.shared.global [%0], [%1], 16;" :: "r"(saddr), "l"(gaddr) : "memory");
}
__device__ __forceinline__ void cp_commit() { asm volatile("cp.async.commit_group;" ::: "memory"); }
__device__ __forceinline__ void cp_wait0()  { asm volatile("cp.async.wait_group 0;" ::: "memory"); }
__device__ __forceinline__ void cp_wait1()  { asm volatile("cp.async.wait_group 1;" ::: "memory"); }
__device__ __forceinline__ void cp_wait2()  { asm volatile("cp.async.wait_group 2;" ::: "memory"); }

__device__ __forceinline__ void ldmx4(uint32_t* r, uint32_t addr) {
    asm volatile("ldmatrix.sync.aligned.m8n8.x4.shared.b16 {%0,%1,%2,%3}, [%4];"
                 : "=r"(r[0]), "=r"(r[1]), "=r"(r[2]), "=r"(r[3]) : "r"(addr));
}
__device__ __forceinline__ void ldmx4t(uint32_t* r, uint32_t addr) {
    asm volatile("ldmatrix.sync.aligned.m8n8.x4.trans.shared.b16 {%0,%1,%2,%3}, [%4];"
                 : "=r"(r[0]), "=r"(r[1]), "=r"(r[2]), "=r"(r[3]) : "r"(addr));
}
__device__ __forceinline__ void ldmx2t(uint32_t* r, uint32_t addr) {
    asm volatile("ldmatrix.sync.aligned.m8n8.x2.trans.shared.b16 {%0,%1}, [%2];"
                 : "=r"(r[0]), "=r"(r[1]) : "r"(addr));
}
__device__ __forceinline__ void mma_fp16(float* c, const uint32_t* a, uint32_t b0, uint32_t b1) {
    asm volatile(
        "mma.sync.aligned.m16n8k16.row.col.f32.f16.f16.f32 "
        "{%0,%1,%2,%3}, {%4,%5,%6,%7}, {%8,%9}, {%0,%1,%2,%3};"
        : "+f"(c[0]), "+f"(c[1]), "+f"(c[2]), "+f"(c[3])
        : "r"(a[0]), "r"(a[1]), "r"(a[2]), "r"(a[3]), "r"(b0), "r"(b1));
}
__device__ __forceinline__ uint32_t packh2(float lo, float hi) {
    uint32_t u;
    asm("cvt.rn.f16x2.f32 %0, %1, %2;" : "=r"(u) : "f"(hi), "f"(lo));
    return u;
}
__device__ __forceinline__ float exp2_poly(float y) {
    float t = y + 12582912.f;
    float n = t - 12582912.f;
    float f = y - n;
    float p = fmaf(0.0555041f, f, 0.2440313f);
    p = fmaf(p, f, 0.6931472f);
    p = fmaf(p, f, 0.9999252f);
    return __int_as_float(__float_as_int(p) + (__float_as_int(t) << 23));
}
__device__ __forceinline__ float exp2_mufu(float y) {
    float r;
    asm("ex2.approx.f32 %0, %1;" : "=f"(r) : "f"(y));
    return r;
}

// ---------------------------------------------------------------------------
// Fused prep: fp32 -> fp16 for x + all four weight matrices, one launch.
// Element space: [0, 4M) = x, [4M, 8M) = Wq|Wk|Wv|Wo (1M each).
// ---------------------------------------------------------------------------
__global__ void prep_all(const float* __restrict__ x,
                         const float* __restrict__ Wq, const float* __restrict__ Wk,
                         const float* __restrict__ Wv, const float* __restrict__ Wo)
{
    int i = (blockIdx.x * 256 + threadIdx.x) * 4;
    const float* src;
    __half* dst;
    int off;
    if (i < NTOK*DD) {
        src = x; dst = g_xh; off = i;
    } else {
        int j = i - NTOK*DD;
        int w = j >> 20;                 // which weight (1M elems each)
        off = j & ((1 << 20) - 1);
        src = (w == 0) ? Wq : (w == 1) ? Wk : (w == 2) ? Wv : Wo;
        dst = (w == 3) ? g_wobuf : g_wbuf + (size_t)w * DD * DD;
    }
    float4 v = *(const float4*)(src + off);
    *(__half2*)(dst + off)     = __floats2half2_rn(v.x, v.y);
    *(__half2*)(dst + off + 2) = __floats2half2_rn(v.z, v.w);
}

// ---------------------------------------------------------------------------
// HMMA GEMM (single fp16): C[4096,1024] = A[4096,1024] @ W[1024,1024]^T + bias
// half_out=1: fp16 out (z==0 scaled by QSCALE). half_out=0: fp32 out.
// ---------------------------------------------------------------------------
__device__ __forceinline__ void load_chunk(uint32_t stage_base,
    const __half* __restrict__ A, const __half* __restrict__ Wz,
    int mBase, int nBase, int chunk, int tid)
{
    const __half* Ab = A  + (size_t)mBase * DD + chunk * 32;
    const __half* Bb = Wz + (size_t)nBase * DD + chunk * 32;
    #pragma unroll
    for (int j = 0; j < 2; j++) {
        int idx = tid + j * 256;
        int row = idx >> 2, g = idx & 3;
        cpasync16(stage_base + row * ROWB + g * 16,          Ab + (size_t)row * DD + g * 8);
        cpasync16(stage_base + A_HALF + row * ROWB + g * 16, Bb + (size_t)row * DD + g * 8);
    }
}

__global__ __launch_bounds__(256, 2) void mma_gemm(
    const __half* __restrict__ A, const __half* __restrict__ W,
    const float* b0p, const float* b1p, const float* b2p,
    float* o0, __half* h0, __half* h1, __half* h2, int half_out)
{
    extern __shared__ char sm_raw[];
    const uint32_t smem = smem_u32(sm_raw);

    const int tid = threadIdx.x;
    const int wid = tid >> 5, lid = tid & 31;
    const int warpM = wid >> 2;
    const int warpN = wid & 3;
    const int nBase = blockIdx.x * 128;
    const int mBase = blockIdx.y * 128;
    const int z = blockIdx.z;
    const __half* Wz = W + (size_t)z * DD * DD;
    const float* bias = (z == 0) ? b0p : (z == 1) ? b1p : b2p;

    float acc[4][4][4];
    #pragma unroll
    for (int mi = 0; mi < 4; mi++)
        #pragma unroll
        for (int nj = 0; nj < 4; nj++)
            #pragma unroll
            for (int e = 0; e < 4; e++) acc[mi][nj][e] = 0.f;

    const uint32_t aOff = (uint32_t)(warpM * 64 + (lid & 15)) * ROWB + ((lid >> 4) << 4);
    const uint32_t bOff = A_HALF +
        (uint32_t)(warpN * 32 + (lid & 7) + ((lid >> 4) << 3)) * ROWB + (((lid >> 3) & 1) << 4);

    #pragma unroll
    for (int s = 0; s < NST - 1; s++) {
        load_chunk(smem + s * STAGE_B, A, Wz, mBase, nBase, s, tid);
        cp_commit();
    }

    for (int i = 0; i < NCH; i++) {
        const uint32_t st = smem + (i & (NST - 1)) * STAGE_B;
        cp_wait2();
        __syncthreads();

        int nxt = i + NST - 1;
        if (nxt < NCH) {
            load_chunk(smem + (nxt & (NST - 1)) * STAGE_B, A, Wz, mBase, nBase, nxt, tid);
            cp_commit();
        }

        #pragma unroll
        for (int kp = 0; kp < 2; kp++) {
            const uint32_t kOff = kp * 32;
            uint32_t af[4][4], bf[2][4];
            #pragma unroll
            for (int mi = 0; mi < 4; mi++)
                ldmx4(af[mi], st + aOff + mi * (16 * ROWB) + kOff);
            #pragma unroll
            for (int g = 0; g < 2; g++)
                ldmx4(bf[g], st + bOff + g * (16 * ROWB) + kOff);
            #pragma unroll
            for (int mi = 0; mi < 4; mi++)
                #pragma unroll
                for (int nj = 0; nj < 4; nj++)
                    mma_fp16(acc[mi][nj], af[mi], bf[nj >> 1][(nj & 1) * 2], bf[nj >> 1][(nj & 1) * 2 + 1]);
        }
    }

    const int rBase = mBase + warpM * 64 + (lid >> 2);
    const int cBase = nBase + warpN * 32 + (lid & 3) * 2;
    if (half_out) {
        __half* hp = (z == 0) ? h0 : (z == 1) ? h1 : h2;
        const float sc = (z == 0) ? QSCALE : 1.f;
        #pragma unroll
        for (int mi = 0; mi < 4; mi++) {
            #pragma unroll
            for (int nj = 0; nj < 4; nj++) {
                int col = cBase + nj * 8;
                float bx = bias[col], by = bias[col + 1];
                int r0 = rBase + mi * 16;
                __half2 v0 = __floats2half2_rn((acc[mi][nj][0] + bx) * sc, (acc[mi][nj][1] + by) * sc);
                __half2 v1 = __floats2half2_rn((acc[mi][nj][2] + bx) * sc, (acc[mi][nj][3] + by) * sc);
                *(__half2*)(hp + (size_t)r0 * DD + col)       = v0;
                *(__half2*)(hp + (size_t)(r0 + 8) * DD + col) = v1;
            }
        }
    } else {
        #pragma unroll
        for (int mi = 0; mi < 4; mi++) {
            #pragma unroll
            for (int nj = 0; nj < 4; nj++) {
                int col = cBase + nj * 8;
                float bx = bias[col], by = bias[col + 1];
                int r0 = rBase + mi * 16;
                float2 v0 = { acc[mi][nj][0] + bx, acc[mi][nj][1] + by };
                float2 v1 = { acc[mi][nj][2] + bx, acc[mi][nj][3] + by };
                *(float2*)(o0 + (size_t)r0 * DD + col)       = v0;
                *(float2*)(o0 + (size_t)(r0 + 8) * DD + col) = v1;
            }
        }
    }
}

// ---------------------------------------------------------------------------
// Tensorized causal flash attention (fp16 mma, no-max softmax, log2 domain).
// __launch_bounds__(256, 2): 2 CTAs/SM so one CTA's exp phase overlaps the
// other's mma phase. Writes ctx directly in fp16.
// ---------------------------------------------------------------------------
__global__ __launch_bounds__(256, 2) void flash_mma()
{
    __shared__ __align__(1024) char sm_f[FSMEM];
    const uint32_t base = smem_u32(sm_f);

    const int tid = threadIdx.x;
    const int wid = tid >> 5, lid = tid & 31;
    const int qt = 15 - blockIdx.x;
    const int h  = blockIdx.y;
    const int b  = blockIdx.z;
    const int qb = qt * 128;
    const int nk = (qt + 1) * 2;

    const __half* qp  = g_qh + (size_t)(b * TT + qb) * DD + h * DH;
    const __half* kp0 = g_kh + (size_t)(b * TT) * DD + h * DH;
    const __half* vp0 = g_vh + (size_t)(b * TT) * DD + h * DH;

    // stage Q through smem, grab A-frags
    #pragma unroll
    for (int j = 0; j < 4; j++) {
        int idx = tid + j * 256;
        int row = idx >> 3, g = idx & 7;
        cpasync16(base + row * FROW + g * 16, qp + (size_t)row * DD + g * 8);
    }
    cp_commit(); cp_wait0();
    __syncthreads();
    uint32_t qf[4][4];
    const uint32_t qaddr = base + (uint32_t)(wid * 16 + (lid & 15)) * FROW + ((lid >> 4) << 4);
    #pragma unroll
    for (int ks = 0; ks < 4; ks++) ldmx4(qf[ks], qaddr + ks * 32);
    __syncthreads();

    // ones columns for both V stages
    if (tid < 128) {
        int s = tid >> 6, r = tid & 63;
        uint4 ones = { 0x3C003C00u, 0x3C003C00u, 0x3C003C00u, 0x3C003C00u };
        *(uint4*)(sm_f + s * FSTG + FSTG_K + r * FROW + 128) = ones;
    }

    // preload ktile 0
    {
        #pragma unroll
        for (int j = 0; j < 2; j++) {
            int idx = tid + j * 256;
            int row = idx >> 3, g = idx & 7;
            cpasync16(base + row * FROW + g * 16,          kp0 + (size_t)row * DD + g * 8);
            cpasync16(base + FSTG_K + row * FROW + g * 16, vp0 + (size_t)row * DD + g * 8);
        }
        cp_commit();
    }

    float of[9][4];
    #pragma unroll
    for (int t = 0; t < 9; t++)
        #pragma unroll
        for (int e = 0; e < 4; e++) of[t][e] = 0.f;

    const uint32_t kfOff = (uint32_t)((lid & 7) + ((lid >> 4) << 3)) * FROW + (((lid >> 3) & 1) << 4);
    const uint32_t vfOff = (uint32_t)((lid & 7) + (((lid >> 3) & 1) << 3)) * FROW + ((lid >> 4) << 4);
    const uint32_t vsOff = (uint32_t)((lid & 7) + (((lid >> 3) & 1) << 3)) * FROW + 128;

    for (int kt = 0; kt < nk; kt++) {
        const int s = kt & 1;
        const int kb = kt * 64;
        __syncthreads();
        if (kt + 1 < nk) {
            const __half* kp = kp0 + (size_t)(kb + 64) * DD;
            const __half* vp = vp0 + (size_t)(kb + 64) * DD;
            uint32_t sb = base + (s ^ 1) * FSTG;
            #pragma unroll
            for (int j = 0; j < 2; j++) {
                int idx = tid + j * 256;
                int row = idx >> 3, g = idx & 7;
                cpasync16(sb + row * FROW + g * 16,          kp + (size_t)row * DD + g * 8);
                cpasync16(sb + FSTG_K + row * FROW + g * 16, vp + (size_t)row * DD + g * 8);
            }
            cp_commit(); cp_wait1();
        } else {
            cp_wait0();
        }
        __syncthreads();

        const uint32_t st = base + s * FSTG;

        float sf[8][4];
        #pragma unroll
        for (int t = 0; t < 8; t++)
            #pragma unroll
            for (int e = 0; e < 4; e++) sf[t][e] = 0.f;

        #pragma unroll
        for (int ks = 0; ks < 4; ks++) {
            uint32_t bf[4][4];
            #pragma unroll
            for (int t = 0; t < 4; t++)
                ldmx4(bf[t], st + kfOff + t * (16 * FROW) + ks * 32);
            #pragma unroll
            for (int nt = 0; nt < 8; nt++)
                mma_fp16(sf[nt], qf[ks], bf[nt >> 1][(nt & 1) * 2], bf[nt >> 1][(nt & 1) * 2 + 1]);
        }

        if (kb + 63 > qb) {
            const int r0 = qb + wid * 16 + (lid >> 2);
            const int c0 = kb + 2 * (lid & 3);
            #pragma unroll
            for (int nt = 0; nt < 8; nt++)
                #pragma unroll
                for (int e = 0; e < 4; e++) {
                    int col = c0 + nt * 8 + (e & 1);
                    int row = r0 + (e >> 1) * 8;
                    if (col > row) sf[nt][e] = -60.f;
                }
        }

        // P = exp2(S): half on MUFU, half on FMA-pipe poly (pipe balance)
        uint32_t pf[8][2];
        #pragma unroll
        for (int nt = 0; nt < 8; nt++) {
            float p0, p1, p2, p3;
            if (nt & 1) {
                p0 = exp2_mufu(sf[nt][0]); p1 = exp2_mufu(sf[nt][1]);
                p2 = exp2_mufu(sf[nt][2]); p3 = exp2_mufu(sf[nt][3]);
            } else {
                p0 = exp2_poly(sf[nt][0]); p1 = exp2_poly(sf[nt][1]);
                p2 = exp2_poly(sf[nt][2]); p3 = exp2_poly(sf[nt][3]);
            }
            pf[nt][0] = packh2(p0, p1);
            pf[nt][1] = packh2(p2, p3);
        }

        #pragma unroll
        for (int ks = 0; ks < 4; ks++) {
            uint32_t pa[4] = { pf[2*ks][0], pf[2*ks][1], pf[2*ks+1][0], pf[2*ks+1][1] };
            uint32_t vrow = st + FSTG_K + ks * (16 * FROW);
            uint32_t vf[4][4], vs[2];
            #pragma unroll
            for (int t = 0; t < 4; t++)
                ldmx4t(vf[t], vrow + vfOff + t * 32);
            ldmx2t(vs, vrow + vsOff);
            #pragma unroll
            for (int dt = 0; dt < 8; dt++)
                mma_fp16(of[dt], pa, vf[dt >> 1][(dt & 1) * 2], vf[dt >> 1][(dt & 1) * 2 + 1]);
            mma_fp16(of[8], pa, vs[0], vs[1]);
        }
    }

    // epilogue: normalize, write ctx fp16
    const float inv0 = 1.f / of[8][0];
    const float inv1 = 1.f / of[8][2];
    const int r = qb + wid * 16 + (lid >> 2);
    const int c = h * DH + 2 * (lid & 3);
    __half* o0 = g_ch + (size_t)(b * TT + r) * DD + c;
    __half* o1 = g_ch + (size_t)(b * TT + r + 8) * DD + c;
    #pragma unroll
    for (int nt = 0; nt < 8; nt++) {
        *(__half2*)(o0 + nt * 8) = __floats2half2_rn(of[nt][0] * inv0, of[nt][1] * inv0);
        *(__half2*)(o1 + nt * 8) = __floats2half2_rn(of[nt][2] * inv1, of[nt][3] * inv1);
    }
}

// ---------------------------------------------------------------------------
extern "C" void kernel_launch(void* const* d_in, const int* in_sizes, int n_in,
                              void* d_out, int out_size)
{
    (void)in_sizes; (void)n_in; (void)out_size;
    const float* x  = (const float*)d_in[0];
    const float* Wq = (const float*)d_in[1];
    const float* bq = (const float*)d_in[2];
    const float* Wk = (const float*)d_in[3];
    const float* bk = (const float*)d_in[4];
    const float* Wv = (const float*)d_in[5];
    const float* bv = (const float*)d_in[6];
    const float* Wo = (const float*)d_in[7];
    const float* bo = (const float*)d_in[8];
    float* out = (float*)d_out;

    __half *xh, *qh, *kh, *vh, *ch, *wbuf, *wobuf;
    cudaGetSymbolAddress((void**)&xh,    g_xh);
    cudaGetSymbolAddress((void**)&qh,    g_qh);
    cudaGetSymbolAddress((void**)&kh,    g_kh);
    cudaGetSymbolAddress((void**)&vh,    g_vh);
    cudaGetSymbolAddress((void**)&ch,    g_ch);
    cudaGetSymbolAddress((void**)&wbuf,  g_wbuf);
    cudaGetSymbolAddress((void**)&wobuf, g_wobuf);

    cudaFuncSetAttribute(mma_gemm,
                         cudaFuncAttributeMaxDynamicSharedMemorySize, GEMM_SMEM);

    // fused prep: x + 4 weights, one launch (8M elems / 4 per thread)
    prep_all<<<(NTOK*DD + 4*DD*DD) / 1024, 256>>>(x, Wq, Wk, Wv, Wo);

    // fused QKV projections -> fp16 (Q pre-scaled into log2 domain)
    mma_gemm<<<dim3(DD/128, NTOK/128, 3), 256, GEMM_SMEM>>>(
        xh, wbuf, bq, bk, bv, nullptr, qh, kh, vh, 1);

    // tensorized causal flash attention (writes ctx fp16)
    flash_mma<<<dim3(TT/128, HH, BB), 256>>>();

    // output projection (fp32 out + bias)
    mma_gemm<<<dim3(DD/128, NTOK/128, 1), 256, GEMM_SMEM>>>(
        ch, wobuf, bo, bo, bo, out, nullptr, nullptr, nullptr, 0);
}

// round 8
// speedup vs baseline: 7.7049x; 1.1192x over previous
#include <cuda_runtime.h>
#include <cuda_fp16.h>
#include <math.h>
#include <stdint.h>

#define BB 2
#define TT 2048
#define DD 1024
#define HH 16
#define DH 64
#define NTOK (BB*TT)
#define NCH 16                  // 1024 / 64 K-chunks
#define NST 2                   // gemm pipeline stages
#define ROWB 144                // gemm smem row stride bytes (128B data + 16 pad)
#define A_BYTES (128*ROWB)      // 18432
#define STAGE_B (A_BYTES + 64*ROWB)  // 27648
#define GEMM_SMEM (NST*STAGE_B)      // 55296
#define QSCALE 0.1803368801f    // log2(e) / sqrt(64)

// flash smem geometry
#define FROW 144
#define FSTG_K 9216
#define FSTG   18432
#define FSMEM  36864

// Scratch (allocation forbidden; __device__ globals are the sanctioned path)
__device__ __half g_xh[NTOK*DD];                    // x in fp16
__device__ __half g_qh[NTOK*DD];                    // pre-scaled by QSCALE
__device__ __half g_kh[NTOK*DD];
__device__ __half g_vh[NTOK*DD];
__device__ __half g_ch[NTOK*DD];                    // ctx in fp16
__device__ __half g_wbuf[(size_t)3*DD*DD];          // Wq|Wk|Wv fp16
__device__ __half g_wobuf[(size_t)DD*DD];           // Wo fp16

// ---------------------------------------------------------------------------
// PTX helpers
// ---------------------------------------------------------------------------
__device__ __forceinline__ uint32_t smem_u32(const void* p) {
    uint32_t a;
    asm("{ .reg .u64 t; cvta.to.shared.u64 t, %1; cvt.u32.u64 %0, t; }" : "=r"(a) : "l"(p));
    return a;
}
__device__ __forceinline__ void cpasync16(uint32_t saddr, const void* gaddr) {
    asm volatile("cp.async.cg.shared.global [%0], [%1], 16;" :: "r"(saddr), "l"(gaddr) : "memory");
}
__device__ __forceinline__ void cp_commit() { asm volatile("cp.async.commit_group;" ::: "memory"); }
__device__ __forceinline__ void cp_wait0()  { asm volatile("cp.async.wait_group 0;" ::: "memory"); }
__device__ __forceinline__ void cp_wait1()  { asm volatile("cp.async.wait_group 1;" ::: "memory"); }

__device__ __forceinline__ void ldmx4(uint32_t* r, uint32_t addr) {
    asm volatile("ldmatrix.sync.aligned.m8n8.x4.shared.b16 {%0,%1,%2,%3}, [%4];"
                 : "=r"(r[0]), "=r"(r[1]), "=r"(r[2]), "=r"(r[3]) : "r"(addr));
}
__device__ __forceinline__ void ldmx4t(uint32_t* r, uint32_t addr) {
    asm volatile("ldmatrix.sync.aligned.m8n8.x4.trans.shared.b16 {%0,%1,%2,%3}, [%4];"
                 : "=r"(r[0]), "=r"(r[1]), "=r"(r[2]), "=r"(r[3]) : "r"(addr));
}
__device__ __forceinline__ void ldmx2t(uint32_t* r, uint32_t addr) {
    asm volatile("ldmatrix.sync.aligned.m8n8.x2.trans.shared.b16 {%0,%1}, [%2];"
                 : "=r"(r[0]), "=r"(r[1]) : "r"(addr));
}
__device__ __forceinline__ void mma_fp16(float* c, const uint32_t* a, uint32_t b0, uint32_t b1) {
    asm volatile(
        "mma.sync.aligned.m16n8k16.row.col.f32.f16.f16.f32 "
        "{%0,%1,%2,%3}, {%4,%5,%6,%7}, {%8,%9}, {%0,%1,%2,%3};"
        : "+f"(c[0]), "+f"(c[1]), "+f"(c[2]), "+f"(c[3])
        : "r"(a[0]), "r"(a[1]), "r"(a[2]), "r"(a[3]), "r"(b0), "r"(b1));
}
__device__ __forceinline__ uint32_t packh2(float lo, float hi) {
    uint32_t u;
    asm("cvt.rn.f16x2.f32 %0, %1, %2;" : "=r"(u) : "f"(hi), "f"(lo));
    return u;
}
__device__ __forceinline__ float exp2_poly(float y) {
    float t = y + 12582912.f;
    float n = t - 12582912.f;
    float f = y - n;
    float p = fmaf(0.0555041f, f, 0.2440313f);
    p = fmaf(p, f, 0.6931472f);
    p = fmaf(p, f, 0.9999252f);
    return __int_as_float(__float_as_int(p) + (__float_as_int(t) << 23));
}
__device__ __forceinline__ float exp2_mufu(float y) {
    float r;
    asm("ex2.approx.f32 %0, %1;" : "=f"(r) : "f"(y));
    return r;
}

// ---------------------------------------------------------------------------
// Fused prep: fp32 -> fp16 for x + all four weight matrices, one launch.
// ---------------------------------------------------------------------------
__global__ void prep_all(const float* __restrict__ x,
                         const float* __restrict__ Wq, const float* __restrict__ Wk,
                         const float* __restrict__ Wv, const float* __restrict__ Wo)
{
    int i = (blockIdx.x * 256 + threadIdx.x) * 4;
    const float* src;
    __half* dst;
    int off;
    if (i < NTOK*DD) {
        src = x; dst = g_xh; off = i;
    } else {
        int j = i - NTOK*DD;
        int w = j >> 20;
        off = j & ((1 << 20) - 1);
        src = (w == 0) ? Wq : (w == 1) ? Wk : (w == 2) ? Wv : Wo;
        dst = (w == 3) ? g_wobuf : g_wbuf + (size_t)w * DD * DD;
    }
    float4 v = *(const float4*)(src + off);
    *(__half2*)(dst + off)     = __floats2half2_rn(v.x, v.y);
    *(__half2*)(dst + off + 2) = __floats2half2_rn(v.z, v.w);
}

// ---------------------------------------------------------------------------
// HMMA GEMM: C[4096,1024] = A[4096,1024] @ W[1024,1024]^T + bias
// CTA: 128 threads, tile 128(M)x64(N), 4 warps (2Mx2N), warp tile 64x32.
// BK=64, 2-stage cp.async pipeline, 4 CTAs/SM.
// grid = (N/64, M/128, z).  half_out=1: fp16 out (z==0 scaled by QSCALE).
// ---------------------------------------------------------------------------
__device__ __forceinline__ void load_chunk(uint32_t stage_base,
    const __half* __restrict__ A, const __half* __restrict__ Wz,
    int mBase, int nBase, int chunk, int tid)
{
    const __half* Ab = A  + (size_t)mBase * DD + chunk * 64;
    const __half* Bb = Wz + (size_t)nBase * DD + chunk * 64;
    #pragma unroll
    for (int j = 0; j < 8; j++) {          // A: 128 rows x 8 granules(16B)
        int idx = tid + j * 128;
        int row = idx >> 3, g = idx & 7;
        cpasync16(stage_base + row * ROWB + g * 16, Ab + (size_t)row * DD + g * 8);
    }
    #pragma unroll
    for (int j = 0; j < 4; j++) {          // B: 64 rows x 8 granules
        int idx = tid + j * 128;
        int row = idx >> 3, g = idx & 7;
        cpasync16(stage_base + A_BYTES + row * ROWB + g * 16, Bb + (size_t)row * DD + g * 8);
    }
}

__global__ __launch_bounds__(128, 4) void mma_gemm(
    const __half* __restrict__ A, const __half* __restrict__ W,
    const float* b0p, const float* b1p, const float* b2p,
    float* o0, __half* h0, __half* h1, __half* h2, int half_out)
{
    extern __shared__ char sm_raw[];
    const uint32_t smem = smem_u32(sm_raw);

    const int tid = threadIdx.x;
    const int wid = tid >> 5, lid = tid & 31;
    const int warpM = wid >> 1;            // 0..1 -> 64-row slab
    const int warpN = wid & 1;             // 0..1 -> 32-col slab
    const int nBase = blockIdx.x * 64;
    const int mBase = blockIdx.y * 128;
    const int z = blockIdx.z;
    const __half* Wz = W + (size_t)z * DD * DD;
    const float* bias = (z == 0) ? b0p : (z == 1) ? b1p : b2p;

    float acc[4][4][4];
    #pragma unroll
    for (int mi = 0; mi < 4; mi++)
        #pragma unroll
        for (int nj = 0; nj < 4; nj++)
            #pragma unroll
            for (int e = 0; e < 4; e++) acc[mi][nj][e] = 0.f;

    const uint32_t aOff = (uint32_t)(warpM * 64 + (lid & 15)) * ROWB + ((lid >> 4) << 4);
    const uint32_t bOff = A_BYTES +
        (uint32_t)(warpN * 32 + (lid & 7) + ((lid >> 4) << 3)) * ROWB + (((lid >> 3) & 1) << 4);

    // prologue: stage 0
    load_chunk(smem, A, Wz, mBase, nBase, 0, tid);
    cp_commit();

    for (int i = 0; i < NCH; i++) {
        const uint32_t st = smem + (i & 1) * STAGE_B;
        cp_wait0();                 // chunk i landed (issued a full compute phase ago)
        __syncthreads();            // all warps done with the stage being overwritten

        if (i + 1 < NCH)
            load_chunk(smem + ((i + 1) & 1) * STAGE_B, A, Wz, mBase, nBase, i + 1, tid);
        cp_commit();                // async; overlaps with compute below

        #pragma unroll
        for (int kp = 0; kp < 4; kp++) {
            const uint32_t kOff = kp * 32;  // 16 halves per kp
            uint32_t af[4][4], bf[2][4];
            #pragma unroll
            for (int mi = 0; mi < 4; mi++)
                ldmx4(af[mi], st + aOff + mi * (16 * ROWB) + kOff);
            #pragma unroll
            for (int g = 0; g < 2; g++)
                ldmx4(bf[g], st + bOff + g * (16 * ROWB) + kOff);
            #pragma unroll
            for (int mi = 0; mi < 4; mi++)
                #pragma unroll
                for (int nj = 0; nj < 4; nj++)
                    mma_fp16(acc[mi][nj], af[mi], bf[nj >> 1][(nj & 1) * 2], bf[nj >> 1][(nj & 1) * 2 + 1]);
        }
        __syncthreads();            // compute done before next overwrite
    }

    const int rBase = mBase + warpM * 64 + (lid >> 2);
    const int cBase = nBase + warpN * 32 + (lid & 3) * 2;
    if (half_out) {
        __half* hp = (z == 0) ? h0 : (z == 1) ? h1 : h2;
        const float sc = (z == 0) ? QSCALE : 1.f;
        #pragma unroll
        for (int mi = 0; mi < 4; mi++) {
            #pragma unroll
            for (int nj = 0; nj < 4; nj++) {
                int col = cBase + nj * 8;
                float bx = bias[col], by = bias[col + 1];
                int r0 = rBase + mi * 16;
                __half2 v0 = __floats2half2_rn((acc[mi][nj][0] + bx) * sc, (acc[mi][nj][1] + by) * sc);
                __half2 v1 = __floats2half2_rn((acc[mi][nj][2] + bx) * sc, (acc[mi][nj][3] + by) * sc);
                *(__half2*)(hp + (size_t)r0 * DD + col)       = v0;
                *(__half2*)(hp + (size_t)(r0 + 8) * DD + col) = v1;
            }
        }
    } else {
        #pragma unroll
        for (int mi = 0; mi < 4; mi++) {
            #pragma unroll
            for (int nj = 0; nj < 4; nj++) {
                int col = cBase + nj * 8;
                float bx = bias[col], by = bias[col + 1];
                int r0 = rBase + mi * 16;
                float2 v0 = { acc[mi][nj][0] + bx, acc[mi][nj][1] + by };
                float2 v1 = { acc[mi][nj][2] + bx, acc[mi][nj][3] + by };
                *(float2*)(o0 + (size_t)r0 * DD + col)       = v0;
                *(float2*)(o0 + (size_t)(r0 + 8) * DD + col) = v1;
            }
        }
    }
}

// ---------------------------------------------------------------------------
// Tensorized causal flash attention (fp16 mma, no-max softmax, log2 domain).
// 2 CTAs/SM; writes ctx directly in fp16.  (unchanged from R7)
// ---------------------------------------------------------------------------
__global__ __launch_bounds__(256, 2) void flash_mma()
{
    __shared__ __align__(1024) char sm_f[FSMEM];
    const uint32_t base = smem_u32(sm_f);

    const int tid = threadIdx.x;
    const int wid = tid >> 5, lid = tid & 31;
    const int qt = 15 - blockIdx.x;
    const int h  = blockIdx.y;
    const int b  = blockIdx.z;
    const int qb = qt * 128;
    const int nk = (qt + 1) * 2;

    const __half* qp  = g_qh + (size_t)(b * TT + qb) * DD + h * DH;
    const __half* kp0 = g_kh + (size_t)(b * TT) * DD + h * DH;
    const __half* vp0 = g_vh + (size_t)(b * TT) * DD + h * DH;

    #pragma unroll
    for (int j = 0; j < 4; j++) {
        int idx = tid + j * 256;
        int row = idx >> 3, g = idx & 7;
        cpasync16(base + row * FROW + g * 16, qp + (size_t)row * DD + g * 8);
    }
    cp_commit(); cp_wait0();
    __syncthreads();
    uint32_t qf[4][4];
    const uint32_t qaddr = base + (uint32_t)(wid * 16 + (lid & 15)) * FROW + ((lid >> 4) << 4);
    #pragma unroll
    for (int ks = 0; ks < 4; ks++) ldmx4(qf[ks], qaddr + ks * 32);
    __syncthreads();

    if (tid < 128) {
        int s = tid >> 6, r = tid & 63;
        uint4 ones = { 0x3C003C00u, 0x3C003C00u, 0x3C003C00u, 0x3C003C00u };
        *(uint4*)(sm_f + s * FSTG + FSTG_K + r * FROW + 128) = ones;
    }

    {
        #pragma unroll
        for (int j = 0; j < 2; j++) {
            int idx = tid + j * 256;
            int row = idx >> 3, g = idx & 7;
            cpasync16(base + row * FROW + g * 16,          kp0 + (size_t)row * DD + g * 8);
            cpasync16(base + FSTG_K + row * FROW + g * 16, vp0 + (size_t)row * DD + g * 8);
        }
        cp_commit();
    }

    float of[9][4];
    #pragma unroll
    for (int t = 0; t < 9; t++)
        #pragma unroll
        for (int e = 0; e < 4; e++) of[t][e] = 0.f;

    const uint32_t kfOff = (uint32_t)((lid & 7) + ((lid >> 4) << 3)) * FROW + (((lid >> 3) & 1) << 4);
    const uint32_t vfOff = (uint32_t)((lid & 7) + (((lid >> 3) & 1) << 3)) * FROW + ((lid >> 4) << 4);
    const uint32_t vsOff = (uint32_t)((lid & 7) + (((lid >> 3) & 1) << 3)) * FROW + 128;

    for (int kt = 0; kt < nk; kt++) {
        const int s = kt & 1;
        const int kb = kt * 64;
        __syncthreads();
        if (kt + 1 < nk) {
            const __half* kp = kp0 + (size_t)(kb + 64) * DD;
            const __half* vp = vp0 + (size_t)(kb + 64) * DD;
            uint32_t sb = base + (s ^ 1) * FSTG;
            #pragma unroll
            for (int j = 0; j < 2; j++) {
                int idx = tid + j * 256;
                int row = idx >> 3, g = idx & 7;
                cpasync16(sb + row * FROW + g * 16,          kp + (size_t)row * DD + g * 8);
                cpasync16(sb + FSTG_K + row * FROW + g * 16, vp + (size_t)row * DD + g * 8);
            }
            cp_commit(); cp_wait1();
        } else {
            cp_wait0();
        }
        __syncthreads();

        const uint32_t st = base + s * FSTG;

        float sf[8][4];
        #pragma unroll
        for (int t = 0; t < 8; t++)
            #pragma unroll
            for (int e = 0; e < 4; e++) sf[t][e] = 0.f;

        #pragma unroll
        for (int ks = 0; ks < 4; ks++) {
            uint32_t bf[4][4];
            #pragma unroll
            for (int t = 0; t < 4; t++)
                ldmx4(bf[t], st + kfOff + t * (16 * FROW) + ks * 32);
            #pragma unroll
            for (int nt = 0; nt < 8; nt++)
                mma_fp16(sf[nt], qf[ks], bf[nt >> 1][(nt & 1) * 2], bf[nt >> 1][(nt & 1) * 2 + 1]);
        }

        if (kb + 63 > qb) {
            const int r0 = qb + wid * 16 + (lid >> 2);
            const int c0 = kb + 2 * (lid & 3);
            #pragma unroll
            for (int nt = 0; nt < 8; nt++)
                #pragma unroll
                for (int e = 0; e < 4; e++) {
                    int col = c0 + nt * 8 + (e & 1);
                    int row = r0 + (e >> 1) * 8;
                    if (col > row) sf[nt][e] = -60.f;
                }
        }

        uint32_t pf[8][2];
        #pragma unroll
        for (int nt = 0; nt < 8; nt++) {
            float p0, p1, p2, p3;
            if (nt & 1) {
                p0 = exp2_mufu(sf[nt][0]); p1 = exp2_mufu(sf[nt][1]);
                p2 = exp2_mufu(sf[nt][2]); p3 = exp2_mufu(sf[nt][3]);
            } else {
                p0 = exp2_poly(sf[nt][0]); p1 = exp2_poly(sf[nt][1]);
                p2 = exp2_poly(sf[nt][2]); p3 = exp2_poly(sf[nt][3]);
            }
            pf[nt][0] = packh2(p0, p1);
            pf[nt][1] = packh2(p2, p3);
        }

        #pragma unroll
        for (int ks = 0; ks < 4; ks++) {
            uint32_t pa[4] = { pf[2*ks][0], pf[2*ks][1], pf[2*ks+1][0], pf[2*ks+1][1] };
            uint32_t vrow = st + FSTG_K + ks * (16 * FROW);
            uint32_t vf[4][4], vs[2];
            #pragma unroll
            for (int t = 0; t < 4; t++)
                ldmx4t(vf[t], vrow + vfOff + t * 32);
            ldmx2t(vs, vrow + vsOff);
            #pragma unroll
            for (int dt = 0; dt < 8; dt++)
                mma_fp16(of[dt], pa, vf[dt >> 1][(dt & 1) * 2], vf[dt >> 1][(dt & 1) * 2 + 1]);
            mma_fp16(of[8], pa, vs[0], vs[1]);
        }
    }

    const float inv0 = 1.f / of[8][0];
    const float inv1 = 1.f / of[8][2];
    const int r = qb + wid * 16 + (lid >> 2);
    const int c = h * DH + 2 * (lid & 3);
    __half* o0 = g_ch + (size_t)(b * TT + r) * DD + c;
    __half* o1 = g_ch + (size_t)(b * TT + r + 8) * DD + c;
    #pragma unroll
    for (int nt = 0; nt < 8; nt++) {
        *(__half2*)(o0 + nt * 8) = __floats2half2_rn(of[nt][0] * inv0, of[nt][1] * inv0);
        *(__half2*)(o1 + nt * 8) = __floats2half2_rn(of[nt][2] * inv1, of[nt][3] * inv1);
    }
}

// ---------------------------------------------------------------------------
extern "C" void kernel_launch(void* const* d_in, const int* in_sizes, int n_in,
                              void* d_out, int out_size)
{
    (void)in_sizes; (void)n_in; (void)out_size;
    const float* x  = (const float*)d_in[0];
    const float* Wq = (const float*)d_in[1];
    const float* bq = (const float*)d_in[2];
    const float* Wk = (const float*)d_in[3];
    const float* bk = (const float*)d_in[4];
    const float* Wv = (const float*)d_in[5];
    const float* bv = (const float*)d_in[6];
    const float* Wo = (const float*)d_in[7];
    const float* bo = (const float*)d_in[8];
    float* out = (float*)d_out;

    __half *xh, *qh, *kh, *vh, *ch, *wbuf, *wobuf;
    cudaGetSymbolAddress((void**)&xh,    g_xh);
    cudaGetSymbolAddress((void**)&qh,    g_qh);
    cudaGetSymbolAddress((void**)&kh,    g_kh);
    cudaGetSymbolAddress((void**)&vh,    g_vh);
    cudaGetSymbolAddress((void**)&ch,    g_ch);
    cudaGetSymbolAddress((void**)&wbuf,  g_wbuf);
    cudaGetSymbolAddress((void**)&wobuf, g_wobuf);

    cudaFuncSetAttribute(mma_gemm,
                         cudaFuncAttributeMaxDynamicSharedMemorySize, GEMM_SMEM);

    // fused prep: x + 4 weights, one launch
    prep_all<<<(NTOK*DD + 4*DD*DD) / 1024, 256>>>(x, Wq, Wk, Wv, Wo);

    // fused QKV projections -> fp16 (Q pre-scaled into log2 domain)
    mma_gemm<<<dim3(DD/64, NTOK/128, 3), 128, GEMM_SMEM>>>(
        xh, wbuf, bq, bk, bv, nullptr, qh, kh, vh, 1);

    // tensorized causal flash attention (writes ctx fp16)
    flash_mma<<<dim3(TT/128, HH, BB), 256>>>();

    // output projection (fp32 out + bias)
    mma_gemm<<<dim3(DD/64, NTOK/128, 1), 128, GEMM_SMEM>>>(
        ch, wobuf, bo, bo, bo, out, nullptr, nullptr, nullptr, 0);
}